// round 5
// baseline (speedup 1.0000x reference)
#include <cuda_runtime.h>
#include <math.h>

#define TILE     64
#define THREADS  256

// ---------------------------------------------------------------------------
// Accurate elementwise helpers (robust to --use_fast_math)
// ---------------------------------------------------------------------------

// sin/cos of ang where ang may be up to ~1e4: reduce ang/pi mod 2 in double
// (exact enough: |err| ~1e-13), then sincospif on the [-1,1] fraction.
__device__ __forceinline__ void acc_sincos(float ang, float* s, float* c) {
    double dq = (double)ang * 0.3183098861837906715377675267450287;  // /pi
    double rq = fma(-2.0, rint(0.5 * dq), dq);                       // in [-1,1]
    sincospif((float)rq, s, c);
}

__device__ __forceinline__ float acc_sigmoid(float v) {
    return 1.0f / (1.0f + expf(-v));
}

__device__ __forceinline__ float acc_tanh(float v) {
    float t = expf(-2.0f * fabsf(v));
    float r = (1.0f - t) / (1.0f + t);
    return copysignf(r, v);
}

// ---------------------------------------------------------------------------
// Block GEMM: C[64, Nout] = A[64, K] @ W[K, Nout] (+ optional ReLU)
// A, C in shared memory; W streamed from global in 16-row chunks via sW.
// Thread layout: warp w owns rows w*8..w*8+7; lane tx owns cols tx+32*j.
// A loads are warp-uniform (LDS broadcast), W loads are consecutive (no
// conflicts), C stores are consecutive.
// ---------------------------------------------------------------------------

template<int TN>
__device__ __forceinline__ void gemm_sub4(
    float (&acc)[8][TN], const float* __restrict__ aBase, int ldA,
    const float* __restrict__ sW, int kk4, int tx)
{
    float bf[4][TN];
#pragma unroll
    for (int kk = 0; kk < 4; ++kk)
#pragma unroll
        for (int j = 0; j < TN; ++j)
            bf[kk][j] = sW[(kk4 + kk) * 160 + tx + 32 * j];
#pragma unroll
    for (int i = 0; i < 8; ++i) {
        const float4 a4 = *reinterpret_cast<const float4*>(aBase + i * ldA + kk4);
#pragma unroll
        for (int j = 0; j < TN; ++j) {
            acc[i][j] = fmaf(a4.x, bf[0][j], acc[i][j]);
            acc[i][j] = fmaf(a4.y, bf[1][j], acc[i][j]);
            acc[i][j] = fmaf(a4.z, bf[2][j], acc[i][j]);
            acc[i][j] = fmaf(a4.w, bf[3][j], acc[i][j]);
        }
    }
}

template<int TN, bool RELU>
__device__ __forceinline__ void block_gemm(
    const float* __restrict__ gW, const int K, const int Nout,
    const float* __restrict__ sA, const int ldA,
    float* __restrict__ sC, const int ldC,
    float* __restrict__ sW)
{
    const int tid = threadIdx.x;
    const int tx  = tid & 31;
    const int r0  = (tid >> 5) * 8;
    constexpr int NW = TN * 32;   // padded output width for this layer

    float acc[8][TN];
#pragma unroll
    for (int i = 0; i < 8; ++i)
#pragma unroll
        for (int j = 0; j < TN; ++j) acc[i][j] = 0.0f;

    for (int k0 = 0; k0 < K; k0 += 16) {
        const int kc = min(16, K - k0);   // 16 always, except 8 once (K=152)
        __syncthreads();                  // sW reuse + sA(=prev sC) readiness
        for (int idx = tid; idx < kc * NW; idx += THREADS) {
            const int kk = idx / NW;
            const int n  = idx - kk * NW;
            sW[kk * 160 + n] = (n < Nout) ? gW[(k0 + kk) * Nout + n] : 0.0f;
        }
        __syncthreads();

        const float* aBase = sA + r0 * ldA + k0;
        if (kc == 16) {
            gemm_sub4<TN>(acc, aBase, ldA, sW, 0,  tx);
            gemm_sub4<TN>(acc, aBase, ldA, sW, 4,  tx);
            gemm_sub4<TN>(acc, aBase, ldA, sW, 8,  tx);
            gemm_sub4<TN>(acc, aBase, ldA, sW, 12, tx);
        } else {  // kc == 8
            gemm_sub4<TN>(acc, aBase, ldA, sW, 0, tx);
            gemm_sub4<TN>(acc, aBase, ldA, sW, 4, tx);
        }
    }

#pragma unroll
    for (int i = 0; i < 8; ++i) {
        float* cRow = sC + (r0 + i) * ldC;
#pragma unroll
        for (int j = 0; j < TN; ++j) {
            const int c = tx + 32 * j;
            if (c < Nout) {
                float v = acc[i][j];
                if (RELU) v = fmaxf(v, 0.0f);
                cRow[c] = v;
            }
        }
    }
}

// ---------------------------------------------------------------------------
// Fused dynamic-NeRF kernel: 64 points per CTA, all activations in smem.
// smem layout (floats):
//   sX : 64 x 208  (enc_p cols 0..79 | part1 cols 80..207; later rgb in 0..2)
//   sH : 64 x 144  ping
//   sG : 64 x 144  pong (finally holds dens_out, 136 cols)
//   sY : 64 x 152  (enc_v cols 0..23 | feature cols 24..151)
//   sW : 16 x 160  weight staging chunk
// ---------------------------------------------------------------------------

#define SMEM_FLOATS (64*208 + 64*144 + 64*144 + 64*152 + 16*160)
#define SMEM_BYTES  (SMEM_FLOATS * 4)

__global__ void __launch_bounds__(THREADS, 1)
FusedDynamicNeRF_kernel(
    const float* __restrict__ x,
    const float* __restrict__ w1_0,  const float* __restrict__ w1_1,
    const float* __restrict__ w1_out,
    const float* __restrict__ w2_0,  const float* __restrict__ w2_1,
    const float* __restrict__ w2_2,  const float* __restrict__ w2_out,
    const float* __restrict__ wc_0,  const float* __restrict__ wc_out,
    float* __restrict__ out, const int N)
{
    extern __shared__ float smem[];
    float* sX = smem;                 // 64*208
    float* sH = sX + 64 * 208;        // 64*144
    float* sG = sH + 64 * 144;        // 64*144
    float* sY = sG + 64 * 144;        // 64*152
    float* sW = sY + 64 * 152;        // 16*160

    const int tid  = threadIdx.x;
    const int base = blockIdx.x * TILE;
    const float PI_F = 3.14159265358979f;   // rounds to fl32(pi), matches jnp.pi in f32

    // ---- positional encoding: 64 rows x 4 dims x 10 freqs ----
    for (int t = tid; t < TILE * 40; t += THREADS) {
        const int r = t / 40;
        const int q = t - r * 40;
        const int d = q / 10;
        const int j = q - d * 10;
        const int i = base + r;
        float xv = 0.0f;
        if (i < N) xv = x[i * 7 + d];
        const float freq = PI_F * __int_as_float((127 + j) << 23);  // fl(pi)*2^j, exact
        const float ang  = xv * freq;                               // matches ref rounding
        float s, c;
        acc_sincos(ang, &s, &c);
        sX[r * 208 + d * 20 + j]      = s;
        sX[r * 208 + d * 20 + 10 + j] = c;
    }
    // ---- view encoding: 64 rows x 3 dims x 4 freqs ----
    for (int t = tid; t < TILE * 12; t += THREADS) {
        const int r = t / 12;
        const int q = t - r * 12;
        const int d = q / 4;
        const int j = q - d * 4;
        const int i = base + r;
        float xv = 0.0f;
        if (i < N) xv = x[i * 7 + 4 + d];
        const float freq = PI_F * __int_as_float((127 + j) << 23);
        const float ang  = xv * freq;
        float s, c;
        acc_sincos(ang, &s, &c);
        sY[r * 152 + d * 8 + j]     = s;
        sY[r * 152 + d * 8 + 4 + j] = c;
    }

    // ---- MLP chain (each gemm begins with __syncthreads) ----
    block_gemm<4, true >(w1_0,   80, 128, sX,      208, sH,      144, sW);
    block_gemm<4, true >(w1_1,  128, 128, sH,      144, sG,      144, sW);
    block_gemm<4, false>(w1_out,128, 128, sG,      144, sX + 80, 208, sW); // part1 -> X[80..207]
    block_gemm<4, true >(w2_0,  208, 128, sX,      208, sH,      144, sW);
    block_gemm<4, true >(w2_1,  128, 128, sH,      144, sG,      144, sW);
    block_gemm<4, true >(w2_2,  128, 128, sG,      144, sH,      144, sW);
    block_gemm<5, false>(w2_out,128, 136, sH,      144, sG,      144, sW); // dens_out -> sG

    __syncthreads();
    // scatter feature = dens_out[:, 8:136] into Y cols 24..151
    for (int t = tid; t < TILE * 128; t += THREADS) {
        const int r = t >> 7;
        const int c = t & 127;
        sY[r * 152 + 24 + c] = sG[r * 144 + 8 + c];
    }

    block_gemm<4, true >(wc_0,  152, 128, sY, 152, sH, 144, sW);
    block_gemm<1, false>(wc_out,128,   3, sH, 144, sX, 208, sW);  // rgb -> X[0..2]

    __syncthreads();
    // ---- output: [rgb(3), density(1), tanh(flow)(6), sigmoid(disocc)(2)] ----
    for (int t = tid; t < TILE * 12; t += THREADS) {
        const int r = t / 12;
        const int c = t - r * 12;
        const int i = base + r;
        if (i < N) {
            float v;
            if      (c < 3)   v = sX[r * 208 + c];                       // rgb
            else if (c == 3)  v = sG[r * 144 + 8];                       // density
            else if (c < 10)  v = acc_tanh(sG[r * 144 + (c - 4)]);       // scene_flow
            else              v = acc_sigmoid(sG[r * 144 + 6 + (c - 10)]); // disocc
            out[i * 12 + c] = v;
        }
    }
}

extern "C" void kernel_launch(void* const* d_in, const int* in_sizes, int n_in,
                              void* d_out, int out_size)
{
    (void)n_in; (void)out_size;
    const float* x      = (const float*)d_in[0];
    const float* w1_0   = (const float*)d_in[1];
    const float* w1_1   = (const float*)d_in[2];
    const float* w1_out = (const float*)d_in[3];
    const float* w2_0   = (const float*)d_in[4];
    const float* w2_1   = (const float*)d_in[5];
    const float* w2_2   = (const float*)d_in[6];
    const float* w2_out = (const float*)d_in[7];
    const float* wc_0   = (const float*)d_in[8];
    const float* wc_out = (const float*)d_in[9];
    float* out = (float*)d_out;

    const int N = in_sizes[0] / 7;
    cudaFuncSetAttribute(FusedDynamicNeRF_kernel,
                         cudaFuncAttributeMaxDynamicSharedMemorySize, SMEM_BYTES);
    const int blocks = (N + TILE - 1) / TILE;
    FusedDynamicNeRF_kernel<<<blocks, THREADS, SMEM_BYTES>>>(
        x, w1_0, w1_1, w1_out, w2_0, w2_1, w2_2, w2_out, wc_0, wc_out, out, N);
}

// round 6
// speedup vs baseline: 1.4226x; 1.4226x over previous
#include <cuda_runtime.h>
#include <math.h>

#define TILE     48
#define THREADS  192
#define NWARP    6          // 6 warps x 8 rows = 48 rows

// ---------------------------------------------------------------------------
// Accurate elementwise helpers (robust to --use_fast_math)
// ---------------------------------------------------------------------------
__device__ __forceinline__ void acc_sincos(float ang, float* s, float* c) {
    double dq = (double)ang * 0.3183098861837906715377675267450287;  // /pi
    double rq = fma(-2.0, rint(0.5 * dq), dq);                       // in [-1,1]
    sincospif((float)rq, s, c);
}
__device__ __forceinline__ float acc_sigmoid(float v) {
    return 1.0f / (1.0f + expf(-v));
}
__device__ __forceinline__ float acc_tanh(float v) {
    float t = expf(-2.0f * fabsf(v));
    float r = (1.0f - t) / (1.0f + t);
    return copysignf(r, v);
}

// ---------------------------------------------------------------------------
// cp.async helpers
// ---------------------------------------------------------------------------
__device__ __forceinline__ void cp_async16(float* smem_dst, const float* gsrc) {
    unsigned s = (unsigned)__cvta_generic_to_shared(smem_dst);
    asm volatile("cp.async.ca.shared.global [%0], [%1], 16;\n" :: "r"(s), "l"(gsrc));
}
__device__ __forceinline__ void cp_commit() {
    asm volatile("cp.async.commit_group;\n");
}
__device__ __forceinline__ void cp_wait0() {
    asm volatile("cp.async.wait_group 0;\n" ::: "memory");
}

// ---------------------------------------------------------------------------
// Block GEMM: C[48, Nout] = A[48, K] @ W[K, Nout] (+ optional ReLU)
// A, C in shared memory; W double-buffered through sW via cp.async,
// 16 K-rows per chunk, copy of chunk c+1 overlapped with compute of chunk c,
// ONE __syncthreads per chunk.
// Warp w owns rows 8w..8w+7; lane tx owns cols tx+32*j (j<TN).
// sW chunk layout is flat kc x Nout (stride Nout) — contiguous gmem copy.
// ---------------------------------------------------------------------------

template<int TN>
__device__ __forceinline__ void gemm_sub4(
    float (&acc)[8][TN], const float* __restrict__ aBase, int ldA,
    const float* __restrict__ sWc, int Nout, int kk4, int tx)
{
    float bf[4][TN];
#pragma unroll
    for (int kk = 0; kk < 4; ++kk)
#pragma unroll
        for (int j = 0; j < TN; ++j)
            bf[kk][j] = sWc[(kk4 + kk) * Nout + tx + 32 * j];
#pragma unroll
    for (int i = 0; i < 8; ++i) {
        const float4 a4 = *reinterpret_cast<const float4*>(aBase + i * ldA + kk4);
#pragma unroll
        for (int j = 0; j < TN; ++j) {
            acc[i][j] = fmaf(a4.x, bf[0][j], acc[i][j]);
            acc[i][j] = fmaf(a4.y, bf[1][j], acc[i][j]);
            acc[i][j] = fmaf(a4.z, bf[2][j], acc[i][j]);
            acc[i][j] = fmaf(a4.w, bf[3][j], acc[i][j]);
        }
    }
}

// Issue async copy of one weight chunk (kc x Nout floats, contiguous) into buf.
__device__ __forceinline__ void stage_chunk(
    float* __restrict__ buf, const float* __restrict__ gW,
    int k0, int kc, int Nout, int tid)
{
    const int n4 = (kc * Nout) >> 2;                 // float4 count (always exact)
    const float* src = gW + k0 * Nout;
    for (int t = tid; t < n4; t += THREADS)
        cp_async16(buf + 4 * t, src + 4 * t);
    cp_commit();
}

template<int TN, bool RELU>
__device__ __forceinline__ void block_gemm(
    const float* __restrict__ gW, const int K, const int Nout,
    const float* __restrict__ sA, const int ldA,
    float* __restrict__ sC, const int ldC,
    float* __restrict__ sW)          // 2 buffers of 16*136 floats each (+pad)
{
    const int tid = threadIdx.x;
    const int tx  = tid & 31;
    const int r0  = (tid >> 5) * 8;
    const int nc  = (K + 15) >> 4;   // number of 16-row chunks

    float acc[8][TN];
#pragma unroll
    for (int i = 0; i < 8; ++i)
#pragma unroll
        for (int j = 0; j < TN; ++j) acc[i][j] = 0.0f;

    __syncthreads();                               // prev layer fully done
    stage_chunk(sW, gW, 0, min(16, K), Nout, tid); // prologue: chunk 0 -> buf0

    for (int c = 0; c < nc; ++c) {
        const int k0 = c << 4;
        const int kc = min(16, K - k0);
        float* bufC = sW + ((c & 1) ? (16 * 136) : 0);

        cp_wait0();            // my chunk-c copies arrived
        __syncthreads();       // chunk c visible to all; compute(c-1) done by all

        if (c + 1 < nc) {      // overlap: copy chunk c+1 into the other buffer
            float* bufN = sW + (((c + 1) & 1) ? (16 * 136) : 0);
            stage_chunk(bufN, gW, k0 + 16, min(16, K - k0 - 16), Nout, tid);
        }

        const float* aBase = sA + r0 * ldA + k0;
        gemm_sub4<TN>(acc, aBase, ldA, bufC, Nout, 0, tx);
        gemm_sub4<TN>(acc, aBase, ldA, bufC, Nout, 4, tx);
        if (kc == 16) {
            gemm_sub4<TN>(acc, aBase, ldA, bufC, Nout, 8,  tx);
            gemm_sub4<TN>(acc, aBase, ldA, bufC, Nout, 12, tx);
        }
    }

#pragma unroll
    for (int i = 0; i < 8; ++i) {
        float* cRow = sC + (r0 + i) * ldC;
#pragma unroll
        for (int j = 0; j < TN; ++j) {
            const int col = tx + 32 * j;
            if (col < Nout) {
                float v = acc[i][j];
                if (RELU) v = fmaxf(v, 0.0f);
                cRow[col] = v;
            }
        }
    }
}

// ---------------------------------------------------------------------------
// smem layout (floats):
//   sX : 48 x 208  (enc_p | part1; later enc_v(0..23)+feature(24..151), rgb 160..162)
//   sH : 48 x 128  ping
//   sG : 48 x 136  pong (finally holds dens_out)
//   sW : 2 x (16 x 136) + 32 pad   weight double buffer
// total = 9984 + 6144 + 6528 + 4384 = 27040 floats = 108160 B  -> 2 CTAs/SM
// ---------------------------------------------------------------------------
#define SMEM_FLOATS (48*208 + 48*128 + 48*136 + 2*16*136 + 32)
#define SMEM_BYTES  (SMEM_FLOATS * 4)

__global__ void __launch_bounds__(THREADS, 2)
FusedDynamicNeRF_kernel(
    const float* __restrict__ x,
    const float* __restrict__ w1_0,  const float* __restrict__ w1_1,
    const float* __restrict__ w1_out,
    const float* __restrict__ w2_0,  const float* __restrict__ w2_1,
    const float* __restrict__ w2_2,  const float* __restrict__ w2_out,
    const float* __restrict__ wc_0,  const float* __restrict__ wc_out,
    float* __restrict__ out, const int N)
{
    extern __shared__ float smem[];
    float* sX = smem;                 // 48*208
    float* sH = sX + 48 * 208;        // 48*128
    float* sG = sH + 48 * 128;        // 48*136
    float* sW = sG + 48 * 136;        // 2*16*136 + 32

    const int tid  = threadIdx.x;
    const int base = blockIdx.x * TILE;
    const float PI_F = 3.14159265358979f;   // fl32(pi) == jnp.pi in f32

    // ---- positional encoding: 48 rows x 4 dims x 10 freqs -> sX[0..80) ----
    for (int t = tid; t < TILE * 40; t += THREADS) {
        const int r = t / 40;
        const int q = t - r * 40;
        const int d = q / 10;
        const int j = q - d * 10;
        const int i = base + r;
        float xv = 0.0f;
        if (i < N) xv = x[i * 7 + d];
        const float freq = PI_F * __int_as_float((127 + j) << 23);  // fl(pi)*2^j
        float s, c;
        acc_sincos(xv * freq, &s, &c);
        sX[r * 208 + d * 20 + j]      = s;
        sX[r * 208 + d * 20 + 10 + j] = c;
    }

    // ---- MLP branch 1 + density branch ----
    block_gemm<4, true >(w1_0,   80, 128, sX,      208, sH,      128, sW);
    block_gemm<4, true >(w1_1,  128, 128, sH,      128, sG,      136, sW);
    block_gemm<4, false>(w1_out,128, 128, sG,      136, sX + 80, 208, sW); // part1 -> X[80..208)
    block_gemm<4, true >(w2_0,  208, 128, sX,      208, sH,      128, sW);
    block_gemm<4, true >(w2_1,  128, 128, sH,      128, sG,      136, sW);
    block_gemm<4, true >(w2_2,  128, 128, sG,      136, sH,      128, sW);
    block_gemm<5, false>(w2_out,128, 136, sH,      128, sG,      136, sW); // dens_out -> sG

    __syncthreads();   // sG ready for reads; sX free to overwrite

    // ---- view encoding -> sX[0..24); feature = dens_out[:,8:136] -> sX[24..152) ----
    for (int t = tid; t < TILE * 12; t += THREADS) {
        const int r = t / 12;
        const int q = t - r * 12;
        const int d = q / 4;
        const int j = q - d * 4;
        const int i = base + r;
        float xv = 0.0f;
        if (i < N) xv = x[i * 7 + 4 + d];
        const float freq = PI_F * __int_as_float((127 + j) << 23);
        float s, c;
        acc_sincos(xv * freq, &s, &c);
        sX[r * 208 + d * 8 + j]     = s;
        sX[r * 208 + d * 8 + 4 + j] = c;
    }
    for (int t = tid; t < TILE * 128; t += THREADS) {
        const int r = t >> 7;
        const int c = t & 127;
        sX[r * 208 + 24 + c] = sG[r * 136 + 8 + c];
    }

    // ---- color branch ----
    block_gemm<4, true >(wc_0,  152, 128, sX, 208, sH,       128, sW);
    block_gemm<1, false>(wc_out,128,   3, sH, 128, sX + 160, 208, sW);  // rgb -> X[160..163)

    __syncthreads();
    // ---- output: [rgb(3), density(1), tanh(flow)(6), sigmoid(disocc)(2)] ----
    for (int t = tid; t < TILE * 12; t += THREADS) {
        const int r = t / 12;
        const int c = t - r * 12;
        const int i = base + r;
        if (i < N) {
            float v;
            if      (c < 3)   v = sX[r * 208 + 160 + c];                   // rgb
            else if (c == 3)  v = sG[r * 136 + 8];                         // density
            else if (c < 10)  v = acc_tanh(sG[r * 136 + (c - 4)]);         // scene_flow
            else              v = acc_sigmoid(sG[r * 136 + 6 + (c - 10)]); // disocc
            out[i * 12 + c] = v;
        }
    }
}

extern "C" void kernel_launch(void* const* d_in, const int* in_sizes, int n_in,
                              void* d_out, int out_size)
{
    (void)n_in; (void)out_size;
    const float* x      = (const float*)d_in[0];
    const float* w1_0   = (const float*)d_in[1];
    const float* w1_1   = (const float*)d_in[2];
    const float* w1_out = (const float*)d_in[3];
    const float* w2_0   = (const float*)d_in[4];
    const float* w2_1   = (const float*)d_in[5];
    const float* w2_2   = (const float*)d_in[6];
    const float* w2_out = (const float*)d_in[7];
    const float* wc_0   = (const float*)d_in[8];
    const float* wc_out = (const float*)d_in[9];
    float* out = (float*)d_out;

    const int N = in_sizes[0] / 7;
    cudaFuncSetAttribute(FusedDynamicNeRF_kernel,
                         cudaFuncAttributeMaxDynamicSharedMemorySize, SMEM_BYTES);
    const int blocks = (N + TILE - 1) / TILE;
    FusedDynamicNeRF_kernel<<<blocks, THREADS, SMEM_BYTES>>>(
        x, w1_0, w1_1, w1_out, w2_0, w2_1, w2_2, w2_out, wc_0, wc_out, out, N);
}

// round 7
// speedup vs baseline: 1.4342x; 1.0082x over previous
#include <cuda_runtime.h>
#include <math.h>

#define TILE     48
#define THREADS  192
typedef unsigned long long ull;

// ---------------------------------------------------------------------------
// Repacked weights: k-pair interleaved layout, one __device__ scratch buffer.
//   dst[kp*2N + 2c + par] = W[2kp+par][c]
// so an 8-byte load at (kp, c) yields the f32x2 pair (W[2kp][c], W[2kp+1][c]).
// ---------------------------------------------------------------------------
#define OFF_W1_0   0
#define OFF_W1_1   10240
#define OFF_W1_OUT 26624
#define OFF_W2_0   43008
#define OFF_W2_1   69632
#define OFF_W2_2   86016
#define OFF_W2_OUT 102400
#define OFF_WC_0   119808
#define OFF_WC_OUT 139264
#define WPK_TOTAL  139648

__device__ __align__(16) float g_wpk[WPK_TOTAL];

__global__ void repack_kernel(const float* __restrict__ src,
                              float* __restrict__ dst, int K, int N)
{
    const int t = blockIdx.x * blockDim.x + threadIdx.x;
    if (t < K * N) {
        const int rem = t >> 1;          // (kp*2N + 2c + par) >> 1 = kp*N + c
        const int par = t & 1;
        const int c   = rem % N;
        const int kp  = rem / N;
        dst[t] = src[(2 * kp + par) * N + c];
    }
}

// ---------------------------------------------------------------------------
// Accurate elementwise helpers (robust to --use_fast_math)
// ---------------------------------------------------------------------------
__device__ __forceinline__ void acc_sincos(float ang, float* s, float* c) {
    double dq = (double)ang * 0.3183098861837906715377675267450287;  // /pi
    double rq = fma(-2.0, rint(0.5 * dq), dq);                       // in [-1,1]
    sincospif((float)rq, s, c);
}
__device__ __forceinline__ float acc_sigmoid(float v) {
    return 1.0f / (1.0f + expf(-v));
}
__device__ __forceinline__ float acc_tanh(float v) {
    float t = expf(-2.0f * fabsf(v));
    float r = (1.0f - t) / (1.0f + t);
    return copysignf(r, v);
}

// ---------------------------------------------------------------------------
// Packed fp32 FMA (sm_103a FFMA2)
// ---------------------------------------------------------------------------
__device__ __forceinline__ ull fma2(ull a, ull b, ull c) {
    ull d;
    asm("fma.rn.f32x2 %0, %1, %2, %3;" : "=l"(d) : "l"(a), "l"(b), "l"(c));
    return d;
}

// ---------------------------------------------------------------------------
// cp.async helpers
// ---------------------------------------------------------------------------
__device__ __forceinline__ void cp_async16(float* smem_dst, const float* gsrc) {
    unsigned s = (unsigned)__cvta_generic_to_shared(smem_dst);
    asm volatile("cp.async.ca.shared.global [%0], [%1], 16;\n" :: "r"(s), "l"(gsrc));
}
__device__ __forceinline__ void cp_commit() {
    asm volatile("cp.async.commit_group;\n");
}
__device__ __forceinline__ void cp_wait0() {
    asm volatile("cp.async.wait_group 0;\n" ::: "memory");
}

// ---------------------------------------------------------------------------
// GEMM inner sub-block: 4 k-rows (= 2 k-pairs) x 8 rows x TN columns.
// acc[i][j] is an f32x2: .lo accumulates even-k products, .hi odd-k.
// aBase points at (row r0, k0): one broadcast LDS.128 per row gives both pairs.
// bBase = chunk buffer at kp0 (k-pair-interleaved): LDS.64 per (kp, col).
// ---------------------------------------------------------------------------
template<int TN, bool TAIL>
__device__ __forceinline__ void gemm_sub2(
    ull (&acc)[8][TN], const float* __restrict__ aBase, int ldA,
    const float* __restrict__ bBase, int Nout, int tx)
{
    ull b2[2][TN];
#pragma unroll
    for (int kp = 0; kp < 2; ++kp)
#pragma unroll
        for (int j = 0; j < TN; ++j) {
            const int col = tx + 32 * j;
            ull v = 0;
            if (!TAIL || j < TN - 1 || col < Nout)
                v = *reinterpret_cast<const ull*>(bBase + kp * 2 * Nout + 2 * col);
            b2[kp][j] = v;
        }
#pragma unroll
    for (int i = 0; i < 8; ++i) {
        const ulonglong2 a2 = *reinterpret_cast<const ulonglong2*>(aBase + i * ldA);
#pragma unroll
        for (int j = 0; j < TN; ++j) {
            acc[i][j] = fma2(a2.x, b2[0][j], acc[i][j]);
            acc[i][j] = fma2(a2.y, b2[1][j], acc[i][j]);
        }
    }
}

// ---------------------------------------------------------------------------
// Block GEMM: C[48, Nout] = A[48, K] @ W[K, Nout] (+ optional ReLU)
// W pre-repacked (k-pair interleaved), streamed in 16-row chunks, double
// buffered via cp.async with ONE __syncthreads per chunk.
// ---------------------------------------------------------------------------
#define CHUNK 2176   // 16 * 136 floats per staging buffer

template<int TN, bool RELU, bool TAIL>
__device__ __forceinline__ void block_gemm(
    const float* __restrict__ gW, const int K, const int Nout,
    const float* __restrict__ sA, const int ldA,
    float* __restrict__ sC, const int ldC,
    float* __restrict__ sW)
{
    const int tid = threadIdx.x;
    const int tx  = tid & 31;
    const int r0  = (tid >> 5) * 8;
    const int nc  = (K + 15) >> 4;

    ull acc[8][TN];
#pragma unroll
    for (int i = 0; i < 8; ++i)
#pragma unroll
        for (int j = 0; j < TN; ++j) acc[i][j] = 0ull;

    __syncthreads();                       // prev layer fully done, sW free
    {   // prologue: chunk 0 -> buf0 (repacked layout is contiguous per chunk)
        const int n4 = (min(16, K) * Nout) >> 2;
        for (int t = tid; t < n4; t += THREADS)
            cp_async16(sW + 4 * t, gW + 4 * t);
        cp_commit();
    }

    for (int c = 0; c < nc; ++c) {
        const int k0 = c << 4;
        const int kc = min(16, K - k0);
        float* bufC = sW + ((c & 1) ? CHUNK : 0);

        cp_wait0();            // chunk c arrived (my copies)
        __syncthreads();       // visible to all; compute(c-1) done by all

        if (c + 1 < nc) {      // overlap: stage chunk c+1 into other buffer
            float* bufN = sW + (((c + 1) & 1) ? CHUNK : 0);
            const float* src = gW + (k0 + 16) * Nout;
            const int n4 = (min(16, K - k0 - 16) * Nout) >> 2;
            for (int t = tid; t < n4; t += THREADS)
                cp_async16(bufN + 4 * t, src + 4 * t);
            cp_commit();
        }

        const float* aBase = sA + r0 * ldA + k0;
        gemm_sub2<TN, TAIL>(acc, aBase,      ldA, bufC,             Nout, tx);
        gemm_sub2<TN, TAIL>(acc, aBase + 4,  ldA, bufC + 4 * Nout,  Nout, tx);
        if (kc == 16) {
            gemm_sub2<TN, TAIL>(acc, aBase + 8,  ldA, bufC + 8 * Nout,  Nout, tx);
            gemm_sub2<TN, TAIL>(acc, aBase + 12, ldA, bufC + 12 * Nout, Nout, tx);
        }
    }

#pragma unroll
    for (int i = 0; i < 8; ++i) {
        float* cRow = sC + (r0 + i) * ldC;
#pragma unroll
        for (int j = 0; j < TN; ++j) {
            const int col = tx + 32 * j;
            if (col < Nout) {
                const float2 p = *reinterpret_cast<const float2*>(&acc[i][j]);
                float v = p.x + p.y;          // merge even/odd-k partial sums
                if (RELU) v = fmaxf(v, 0.0f);
                cRow[col] = v;
            }
        }
    }
}

// ---------------------------------------------------------------------------
// smem layout (floats):
//   sX : 48 x 208  (enc_p | part1; later enc_v(0..23)+feature(24..151), rgb 160..162)
//   sH : 48 x 128  ping
//   sG : 48 x 136  pong (finally holds dens_out)
//   sW : 2 x CHUNK + 64 pad    weight double buffer
// total = 9984 + 6144 + 6528 + 4416 = 27072 floats = 108288 B -> 2 CTAs/SM
// ---------------------------------------------------------------------------
#define SMEM_FLOATS (48*208 + 48*128 + 48*136 + 2*CHUNK + 64)
#define SMEM_BYTES  (SMEM_FLOATS * 4)

__global__ void __launch_bounds__(THREADS, 2)
FusedDynamicNeRF_kernel(const float* __restrict__ x,
                        float* __restrict__ out, const int N)
{
    extern __shared__ float smem[];
    float* sX = smem;                 // 48*208
    float* sH = sX + 48 * 208;        // 48*128
    float* sG = sH + 48 * 128;        // 48*136
    float* sW = sG + 48 * 136;        // 2*CHUNK + 64

    const int tid  = threadIdx.x;
    const int base = blockIdx.x * TILE;
    const float PI_F = 3.14159265358979f;   // fl32(pi) == jnp.pi in f32

    // ---- positional encoding: 48 rows x 4 dims x 10 freqs -> sX[0..80) ----
    for (int t = tid; t < TILE * 40; t += THREADS) {
        const int r = t / 40;
        const int q = t - r * 40;
        const int d = q / 10;
        const int j = q - d * 10;
        const int i = base + r;
        float xv = 0.0f;
        if (i < N) xv = x[i * 7 + d];
        const float freq = PI_F * __int_as_float((127 + j) << 23);  // fl(pi)*2^j
        float s, c;
        acc_sincos(xv * freq, &s, &c);
        sX[r * 208 + d * 20 + j]      = s;
        sX[r * 208 + d * 20 + 10 + j] = c;
    }

    // ---- MLP branch 1 + density branch ----
    block_gemm<4, true , false>(g_wpk + OFF_W1_0,   80, 128, sX,      208, sH,      128, sW);
    block_gemm<4, true , false>(g_wpk + OFF_W1_1,  128, 128, sH,      128, sG,      136, sW);
    block_gemm<4, false, false>(g_wpk + OFF_W1_OUT,128, 128, sG,      136, sX + 80, 208, sW);
    block_gemm<4, true , false>(g_wpk + OFF_W2_0,  208, 128, sX,      208, sH,      128, sW);
    block_gemm<4, true , false>(g_wpk + OFF_W2_1,  128, 128, sH,      128, sG,      136, sW);
    block_gemm<4, true , false>(g_wpk + OFF_W2_2,  128, 128, sG,      136, sH,      128, sW);
    block_gemm<5, false, true >(g_wpk + OFF_W2_OUT,128, 136, sH,      128, sG,      136, sW);

    __syncthreads();   // sG (dens_out) ready; sX free to overwrite

    // ---- view encoding -> sX[0..24); feature = dens_out[:,8:136] -> sX[24..152) ----
    for (int t = tid; t < TILE * 12; t += THREADS) {
        const int r = t / 12;
        const int q = t - r * 12;
        const int d = q / 4;
        const int j = q - d * 4;
        const int i = base + r;
        float xv = 0.0f;
        if (i < N) xv = x[i * 7 + 4 + d];
        const float freq = PI_F * __int_as_float((127 + j) << 23);
        float s, c;
        acc_sincos(xv * freq, &s, &c);
        sX[r * 208 + d * 8 + j]     = s;
        sX[r * 208 + d * 8 + 4 + j] = c;
    }
    for (int t = tid; t < TILE * 128; t += THREADS) {
        const int r = t >> 7;
        const int c = t & 127;
        sX[r * 208 + 24 + c] = sG[r * 136 + 8 + c];
    }

    // ---- color branch ----
    block_gemm<4, true , false>(g_wpk + OFF_WC_0,  152, 128, sX, 208, sH,       128, sW);
    block_gemm<1, false, true >(g_wpk + OFF_WC_OUT,128,   3, sH, 128, sX + 160, 208, sW);

    __syncthreads();
    // ---- output: [rgb(3), density(1), tanh(flow)(6), sigmoid(disocc)(2)] ----
    for (int t = tid; t < TILE * 12; t += THREADS) {
        const int r = t / 12;
        const int c = t - r * 12;
        const int i = base + r;
        if (i < N) {
            float v;
            if      (c < 3)   v = sX[r * 208 + 160 + c];                   // rgb
            else if (c == 3)  v = sG[r * 136 + 8];                         // density
            else if (c < 10)  v = acc_tanh(sG[r * 136 + (c - 4)]);         // scene_flow
            else              v = acc_sigmoid(sG[r * 136 + 6 + (c - 10)]); // disocc
            out[i * 12 + c] = v;
        }
    }
}

extern "C" void kernel_launch(void* const* d_in, const int* in_sizes, int n_in,
                              void* d_out, int out_size)
{
    (void)n_in; (void)out_size;
    const float* x = (const float*)d_in[0];
    float* out = (float*)d_out;
    const int N = in_sizes[0] / 7;

    float* wpk;
    cudaGetSymbolAddress((void**)&wpk, g_wpk);

    struct { int src; int off, K, Nw; } L[9] = {
        {1, OFF_W1_0,   80, 128}, {2, OFF_W1_1,  128, 128},
        {3, OFF_W1_OUT,128, 128}, {4, OFF_W2_0,  208, 128},
        {5, OFF_W2_1,  128, 128}, {6, OFF_W2_2,  128, 128},
        {7, OFF_W2_OUT,128, 136}, {8, OFF_WC_0,  152, 128},
        {9, OFF_WC_OUT,128,   3}
    };
    for (int l = 0; l < 9; ++l) {
        const int total = L[l].K * L[l].Nw;
        repack_kernel<<<(total + 255) / 256, 256>>>(
            (const float*)d_in[L[l].src], wpk + L[l].off, L[l].K, L[l].Nw);
    }

    cudaFuncSetAttribute(FusedDynamicNeRF_kernel,
                         cudaFuncAttributeMaxDynamicSharedMemorySize, SMEM_BYTES);
    const int blocks = (N + TILE - 1) / TILE;
    FusedDynamicNeRF_kernel<<<blocks, THREADS, SMEM_BYTES>>>(x, out, N);
}

// round 10
// speedup vs baseline: 1.5088x; 1.0520x over previous
#include <cuda_runtime.h>
#include <math.h>

#define TILE     48
#define THREADS  192
typedef unsigned long long ull;

// ---------------------------------------------------------------------------
// Repacked weights: k-pair interleaved layout in one __device__ scratch buffer.
//   dst[kp*2N + 2c + par] = W[2kp+par][c]
// so an 8-byte smem load at (kp, c) yields the f32x2 pair (W[2kp][c], W[2kp+1][c]).
// ---------------------------------------------------------------------------
#define OFF_W1_0   0
#define OFF_W1_1   10240
#define OFF_W1_OUT 26624
#define OFF_W2_0   43008
#define OFF_W2_1   69632
#define OFF_W2_2   86016
#define OFF_W2_OUT 102400
#define OFF_WC_0   119808
#define OFF_WC_OUT 139264
#define WPK_TOTAL  139648

__device__ __align__(16) float g_wpk[WPK_TOTAL];

__global__ void repack_kernel(const float* __restrict__ src,
                              float* __restrict__ dst, int K, int N)
{
    const int t = blockIdx.x * blockDim.x + threadIdx.x;
    if (t < K * N) {
        const int rem = t >> 1;          // (kp*2N + 2c + par) >> 1 = kp*N + c
        const int par = t & 1;
        const int c   = rem % N;
        const int kp  = rem / N;
        dst[t] = src[(2 * kp + par) * N + c];
    }
}

// ---------------------------------------------------------------------------
// Accurate elementwise helpers (robust to --use_fast_math)
// ---------------------------------------------------------------------------
__device__ __forceinline__ void acc_sincos(float ang, float* s, float* c) {
    double dq = (double)ang * 0.3183098861837906715377675267450287;  // /pi
    double rq = fma(-2.0, rint(0.5 * dq), dq);                       // in [-1,1]
    sincospif((float)rq, s, c);
}
__device__ __forceinline__ float acc_sigmoid(float v) {
    return 1.0f / (1.0f + expf(-v));
}
__device__ __forceinline__ float acc_tanh(float v) {
    float t = expf(-2.0f * fabsf(v));
    float r = (1.0f - t) / (1.0f + t);
    return copysignf(r, v);
}

// ---------------------------------------------------------------------------
// Packed fp32 FMA (sm_103a FFMA2 — only reachable via PTX fma.rn.f32x2)
// ---------------------------------------------------------------------------
__device__ __forceinline__ ull fma2(ull a, ull b, ull c) {
    ull d;
    asm("fma.rn.f32x2 %0, %1, %2, %3;" : "=l"(d) : "l"(a), "l"(b), "l"(c));
    return d;
}

// ---------------------------------------------------------------------------
// cp.async helpers
// ---------------------------------------------------------------------------
__device__ __forceinline__ void cp_async16(float* smem_dst, const float* gsrc) {
    unsigned s = (unsigned)__cvta_generic_to_shared(smem_dst);
    asm volatile("cp.async.ca.shared.global [%0], [%1], 16;\n" :: "r"(s), "l"(gsrc));
}
__device__ __forceinline__ void cp_commit() {
    asm volatile("cp.async.commit_group;\n");
}
__device__ __forceinline__ void cp_wait0() {
    asm volatile("cp.async.wait_group 0;\n" ::: "memory");
}

// ---------------------------------------------------------------------------
// GEMM inner sub-block: 4 k-rows (= 2 k-pairs) x 8 rows x TN columns.
// acc[i][j] is f32x2: .lo accumulates even-k partial sums, .hi odd-k.
// A: one warp-uniform LDS.128 per row gives both k-pairs (zero pack MOVs).
// B: k-pair interleaved chunk -> direct conflict-free LDS.64 per (kp, col).
// All dims compile-time: addressing folds to immediates (alu-pipe relief).
// ---------------------------------------------------------------------------
template<int TN, int Nout, int ldA>
__device__ __forceinline__ void gemm_sub2(
    ull (&acc)[8][TN], const float* __restrict__ aBase,
    const float* __restrict__ bBase, int tx)
{
    constexpr bool TAIL = (TN * 32 != Nout);
    ull b2[2][TN];
#pragma unroll
    for (int kp = 0; kp < 2; ++kp)
#pragma unroll
        for (int j = 0; j < TN; ++j) {
            const int col = tx + 32 * j;
            ull v = 0;
            if (!TAIL || j < TN - 1 || col < Nout)
                v = *reinterpret_cast<const ull*>(bBase + kp * 2 * Nout + 2 * col);
            b2[kp][j] = v;
        }
#pragma unroll
    for (int i = 0; i < 8; ++i) {
        const ulonglong2 a2 = *reinterpret_cast<const ulonglong2*>(aBase + i * ldA);
#pragma unroll
        for (int j = 0; j < TN; ++j) {
            acc[i][j] = fma2(a2.x, b2[0][j], acc[i][j]);
            acc[i][j] = fma2(a2.y, b2[1][j], acc[i][j]);
        }
    }
}

// ---------------------------------------------------------------------------
// Block GEMM: C[48, Nout] = A[48, K] @ W[K, Nout] (+ optional ReLU)
// W pre-repacked (k-pair interleaved, contiguous chunks), streamed in 16-row
// chunks, double buffered via cp.async, ONE __syncthreads per chunk.
// ---------------------------------------------------------------------------
#define CHUNK 2176   // 16 * 136 floats per staging buffer

template<int K, int Nout, int ldA, int ldC, int TN, bool RELU>
__device__ __forceinline__ void block_gemm(
    const float* __restrict__ gW,
    const float* __restrict__ sA,
    float* __restrict__ sC,
    float* __restrict__ sW)
{
    const int tid = threadIdx.x;
    const int tx  = tid & 31;
    const int r0  = (tid >> 5) * 8;
    constexpr int nc = (K + 15) >> 4;

    ull acc[8][TN];
#pragma unroll
    for (int i = 0; i < 8; ++i)
#pragma unroll
        for (int j = 0; j < TN; ++j) acc[i][j] = 0ull;

    __syncthreads();                       // prev layer fully done, sW free
    {   // prologue: chunk 0 -> buf0 (repacked layout is contiguous per chunk)
        constexpr int n4 = ((K < 16 ? K : 16) * Nout) >> 2;
        for (int t = tid; t < n4; t += THREADS)
            cp_async16(sW + 4 * t, gW + 4 * t);
        cp_commit();
    }

#pragma unroll
    for (int c = 0; c < nc; ++c) {
        const int k0 = c << 4;
        const int kc = (K - k0 < 16) ? (K - k0) : 16;
        float* bufC = sW + ((c & 1) ? CHUNK : 0);

        cp_wait0();            // chunk c arrived (my copies)
        __syncthreads();       // visible to all; compute(c-1) done by all

        if (c + 1 < nc) {      // overlap: stage chunk c+1 into other buffer
            float* bufN = sW + (((c + 1) & 1) ? CHUNK : 0);
            const float* src = gW + (k0 + 16) * Nout;
            const int kn = (K - k0 - 16 < 16) ? (K - k0 - 16) : 16;
            const int n4 = (kn * Nout) >> 2;
            for (int t = tid; t < n4; t += THREADS)
                cp_async16(bufN + 4 * t, src + 4 * t);
            cp_commit();
        }

        const float* aBase = sA + r0 * ldA + k0;
        gemm_sub2<TN, Nout, ldA>(acc, aBase,     bufC,            tx);
        gemm_sub2<TN, Nout, ldA>(acc, aBase + 4, bufC + 4 * Nout, tx);
        if (kc == 16) {
            gemm_sub2<TN, Nout, ldA>(acc, aBase + 8,  bufC + 8 * Nout,  tx);
            gemm_sub2<TN, Nout, ldA>(acc, aBase + 12, bufC + 12 * Nout, tx);
        }
    }

#pragma unroll
    for (int i = 0; i < 8; ++i) {
        float* cRow = sC + (r0 + i) * ldC;
#pragma unroll
        for (int j = 0; j < TN; ++j) {
            const int col = tx + 32 * j;
            if (col < Nout) {
                const float2 p = *reinterpret_cast<const float2*>(&acc[i][j]);
                float v = p.x + p.y;          // merge even/odd-k partial sums
                if (RELU) v = fmaxf(v, 0.0f);
                cRow[col] = v;
            }
        }
    }
}

// ---------------------------------------------------------------------------
// smem layout (floats):
//   sX : 48 x 208  (enc_p | part1; later enc_v(0..23)+feature(24..151), rgb 160..162)
//   sH : 48 x 128  ping
//   sG : 48 x 136  pong (finally holds dens_out)
//   sW : 2 x CHUNK + 64 pad    weight double buffer
// total = 9984 + 6144 + 6528 + 4416 = 27072 floats = 108288 B -> 2 CTAs/SM
// ---------------------------------------------------------------------------
#define SMEM_FLOATS (48*208 + 48*128 + 48*136 + 2*CHUNK + 64)
#define SMEM_BYTES  (SMEM_FLOATS * 4)

__global__ void __launch_bounds__(THREADS, 2)
FusedDynamicNeRF_kernel(const float* __restrict__ x,
                        float* __restrict__ out, const int N)
{
    extern __shared__ float smem[];
    float* sX = smem;                 // 48*208
    float* sH = sX + 48 * 208;        // 48*128
    float* sG = sH + 48 * 128;        // 48*136
    float* sW = sG + 48 * 136;        // 2*CHUNK + 64

    const int tid  = threadIdx.x;
    const int base = blockIdx.x * TILE;
    const float PI_F = 3.14159265358979f;   // fl32(pi) == jnp.pi in f32

    // ---- positional encoding: 48 rows x 4 dims x 10 freqs -> sX[0..80) ----
    for (int t = tid; t < TILE * 40; t += THREADS) {
        const int r = t / 40;
        const int q = t - r * 40;
        const int d = q / 10;
        const int j = q - d * 10;
        const int i = base + r;
        float xv = 0.0f;
        if (i < N) xv = x[i * 7 + d];
        const float freq = PI_F * __int_as_float((127 + j) << 23);  // fl(pi)*2^j
        float s, c;
        acc_sincos(xv * freq, &s, &c);
        sX[r * 208 + d * 20 + j]      = s;
        sX[r * 208 + d * 20 + 10 + j] = c;
    }

    // ---- MLP branch 1 + density branch ----
    block_gemm< 80, 128, 208, 128, 4, true >(g_wpk + OFF_W1_0,   sX,      sH,      sW);
    block_gemm<128, 128, 128, 136, 4, true >(g_wpk + OFF_W1_1,   sH,      sG,      sW);
    block_gemm<128, 128, 136, 208, 4, false>(g_wpk + OFF_W1_OUT, sG,      sX + 80, sW); // part1
    block_gemm<208, 128, 208, 128, 4, true >(g_wpk + OFF_W2_0,   sX,      sH,      sW);
    block_gemm<128, 128, 128, 136, 4, true >(g_wpk + OFF_W2_1,   sH,      sG,      sW);
    block_gemm<128, 128, 136, 128, 4, true >(g_wpk + OFF_W2_2,   sG,      sH,      sW);
    block_gemm<128, 136, 128, 136, 5, false>(g_wpk + OFF_W2_OUT, sH,      sG,      sW); // dens_out

    __syncthreads();   // sG (dens_out) ready; sX free to overwrite

    // ---- view encoding -> sX[0..24); feature = dens_out[:,8:136] -> sX[24..152) ----
    for (int t = tid; t < TILE * 12; t += THREADS) {
        const int r = t / 12;
        const int q = t - r * 12;
        const int d = q / 4;
        const int j = q - d * 4;
        const int i = base + r;
        float xv = 0.0f;
        if (i < N) xv = x[i * 7 + 4 + d];
        const float freq = PI_F * __int_as_float((127 + j) << 23);
        float s, c;
        acc_sincos(xv * freq, &s, &c);
        sX[r * 208 + d * 8 + j]     = s;
        sX[r * 208 + d * 8 + 4 + j] = c;
    }
    for (int t = tid; t < TILE * 128; t += THREADS) {
        const int r = t >> 7;
        const int c = t & 127;
        sX[r * 208 + 24 + c] = sG[r * 136 + 8 + c];
    }

    // ---- color branch ----
    block_gemm<152, 128, 208, 128, 4, true >(g_wpk + OFF_WC_0,   sX, sH,       sW);
    block_gemm<128,   3, 128, 208, 1, false>(g_wpk + OFF_WC_OUT, sH, sX + 160, sW); // rgb

    __syncthreads();
    // ---- output: [rgb(3), density(1), tanh(flow)(6), sigmoid(disocc)(2)] ----
    for (int t = tid; t < TILE * 12; t += THREADS) {
        const int r = t / 12;
        const int c = t - r * 12;
        const int i = base + r;
        if (i < N) {
            float v;
            if      (c < 3)   v = sX[r * 208 + 160 + c];                   // rgb
            else if (c == 3)  v = sG[r * 136 + 8];                         // density
            else if (c < 10)  v = acc_tanh(sG[r * 136 + (c - 4)]);         // scene_flow
            else              v = acc_sigmoid(sG[r * 136 + 6 + (c - 10)]); // disocc
            out[i * 12 + c] = v;
        }
    }
}

extern "C" void kernel_launch(void* const* d_in, const int* in_sizes, int n_in,
                              void* d_out, int out_size)
{
    (void)n_in; (void)out_size;
    const float* x = (const float*)d_in[0];
    float* out = (float*)d_out;
    const int N = in_sizes[0] / 7;

    float* wpk;
    cudaGetSymbolAddress((void**)&wpk, g_wpk);

    struct { int src; int off, K, Nw; } L[9] = {
        {1, OFF_W1_0,   80, 128}, {2, OFF_W1_1,  128, 128},
        {3, OFF_W1_OUT,128, 128}, {4, OFF_W2_0,  208, 128},
        {5, OFF_W2_1,  128, 128}, {6, OFF_W2_2,  128, 128},
        {7, OFF_W2_OUT,128, 136}, {8, OFF_WC_0,  152, 128},
        {9, OFF_WC_OUT,128,   3}
    };
    for (int l = 0; l < 9; ++l) {
        const int total = L[l].K * L[l].Nw;
        repack_kernel<<<(total + 255) / 256, 256>>>(
            (const float*)d_in[L[l].src], wpk + L[l].off, L[l].K, L[l].Nw);
    }

    cudaFuncSetAttribute(FusedDynamicNeRF_kernel,
                         cudaFuncAttributeMaxDynamicSharedMemorySize, SMEM_BYTES);
    const int blocks = (N + TILE - 1) / TILE;
    FusedDynamicNeRF_kernel<<<blocks, THREADS, SMEM_BYTES>>>(x, out, N);
}

// round 14
// speedup vs baseline: 3.1393x; 2.0807x over previous
#include <cuda_runtime.h>
#include <cuda_bf16.h>
#include <math.h>
#include <stdint.h>

#define THREADS 256
#define MTILE   128

// ---------------------------------------------------------------------------
// Repacked B in global scratch: per layer, chunks of 32 k-columns.
// Chunk layout: [2 splits (hi,lo)][Npad rows(n)][40 bf16 (32 k + 8 pad)]
// so ldmatrix rows are 80B apart (bank-stagger 5 mod 8 -> conflict-free).
// ---------------------------------------------------------------------------
#define WPK_ELEMS 363520
__device__ __align__(16) __nv_bfloat16 g_wpk[WPK_ELEMS];

__global__ void repack_kernel(
    const float* w0, const float* w1, const float* w2, const float* w3,
    const float* w4, const float* w5, const float* w6, const float* w7,
    const float* w8)
{
    const int KR[9]  = {80,128,128,208,128,128,128,152,128};
    const int NR[9]  = {128,128,128,128,128,128,136,128,3};
    const int NP[9]  = {128,128,128,128,128,128,136,128,8};
    const int NC[9]  = {3,4,4,7,4,4,4,5,4};
    const int OFF[9] = {0,30720,71680,112640,184320,225280,266240,309760,360960};
    const float* ws[9] = {w0,w1,w2,w3,w4,w5,w6,w7,w8};

    const int l = blockIdx.y;
    const float* W = ws[l];
    const int np = NP[l], nr = NR[l], kr = KR[l];
    const int per_chunk = 2 * np * 40;
    const int total = NC[l] * per_chunk;
    for (int idx = blockIdx.x * blockDim.x + threadIdx.x; idx < total;
         idx += gridDim.x * blockDim.x) {
        const int c    = idx / per_chunk;
        int rem        = idx - c * per_chunk;
        const int sg   = rem / (np * 40);
        rem           -= sg * (np * 40);
        const int n    = rem / 40;
        const int kk   = rem - n * 40;
        const int k    = c * 32 + kk;
        float v = 0.0f;
        if (kk < 32 && k < kr && n < nr) v = W[k * nr + n];
        const __nv_bfloat16 h = __float2bfloat16_rn(v);
        if (sg == 0) g_wpk[OFF[l] + idx] = h;
        else {
            const float r = v - __bfloat162float(h);
            g_wpk[OFF[l] + idx] = __float2bfloat16_rn(r);
        }
    }
}

// ---------------------------------------------------------------------------
// Helpers
// ---------------------------------------------------------------------------
__device__ __forceinline__ void acc_sincos(float ang, float* s, float* c) {
    double dq = (double)ang * 0.3183098861837906715377675267450287;  // /pi
    double rq = fma(-2.0, rint(0.5 * dq), dq);                       // [-1,1]
    sincospif((float)rq, s, c);
}
__device__ __forceinline__ float acc_sigmoid(float v) { return 1.0f / (1.0f + expf(-v)); }
__device__ __forceinline__ float acc_tanh(float v) {
    float t = expf(-2.0f * fabsf(v));
    return copysignf((1.0f - t) / (1.0f + t), v);
}
__device__ __forceinline__ uint32_t packbf(float lo, float hi) {
    uint32_t r;
    asm("cvt.rn.bf16x2.f32 %0, %1, %2;" : "=r"(r) : "f"(hi), "f"(lo));
    return r;
}
__device__ __forceinline__ float bflo(uint32_t u) { return __uint_as_float(u << 16); }
__device__ __forceinline__ float bfhi(uint32_t u) { return __uint_as_float(u & 0xFFFF0000u); }
// split v0 (low lane), v1 (high lane) into hi-pair h and residual-pair l
__device__ __forceinline__ void split2(float v0, float v1, uint32_t& h, uint32_t& l) {
    h = packbf(v0, v1);
    l = packbf(v0 - bflo(h), v1 - bfhi(h));
}
__device__ __forceinline__ void ldsm2(uint32_t& r0, uint32_t& r1, uint32_t addr) {
    asm volatile("ldmatrix.sync.aligned.m8n8.x2.shared.b16 {%0,%1}, [%2];"
                 : "=r"(r0), "=r"(r1) : "r"(addr));
}
__device__ __forceinline__ void mma_bf16(float (&c)[4],
    uint32_t a0, uint32_t a1, uint32_t a2, uint32_t a3, uint32_t b0, uint32_t b1) {
    asm("mma.sync.aligned.m16n8k16.row.col.f32.bf16.bf16.f32 "
        "{%0,%1,%2,%3}, {%4,%5,%6,%7}, {%8,%9}, {%0,%1,%2,%3};"
        : "+f"(c[0]), "+f"(c[1]), "+f"(c[2]), "+f"(c[3])
        : "r"(a0), "r"(a1), "r"(a2), "r"(a3), "r"(b0), "r"(b1));
}
__device__ __forceinline__ void cp_async16(void* sdst, const void* gsrc) {
    unsigned s = (unsigned)__cvta_generic_to_shared(sdst);
    asm volatile("cp.async.ca.shared.global [%0], [%1], 16;" :: "r"(s), "l"(gsrc));
}
__device__ __forceinline__ void cp_commit() { asm volatile("cp.async.commit_group;"); }
__device__ __forceinline__ void cp_wait0()  {
    asm volatile("cp.async.wait_group 0;" ::: "memory");
}

// ---------------------------------------------------------------------------
// C-fragment -> next-layer A-fragments (in registers, with optional ReLU).
// A kstep s <- C tiles (T0+2s, T0+2s+1): a0=(c0,c1) even tile, a1=(c2,c3),
// a2/a3 from odd tile. Writes AH[s][0..3], AL[s][0..3].
// ---------------------------------------------------------------------------
template<int NS, bool RELU, int T0>
__device__ __forceinline__ void c_to_a(const float (&C)[17][4],
                                       uint32_t (&AH)[8][4], uint32_t (&AL)[8][4]) {
#pragma unroll
    for (int s = 0; s < NS; ++s) {
#pragma unroll
        for (int half = 0; half < 2; ++half) {
            const int t = T0 + 2 * s + half;
            float c0 = C[t][0], c1 = C[t][1], c2 = C[t][2], c3 = C[t][3];
            if (RELU) {
                c0 = fmaxf(c0, 0.f); c1 = fmaxf(c1, 0.f);
                c2 = fmaxf(c2, 0.f); c3 = fmaxf(c3, 0.f);
            }
            uint32_t h01, h23, l01, l23;
            split2(c0, c1, h01, l01);
            split2(c2, c3, h23, l23);
            AH[s][2 * half]     = h01;  AH[s][2 * half + 1] = h23;
            AL[s][2 * half]     = l01;  AL[s][2 * half + 1] = l23;
        }
    }
}

// ---------------------------------------------------------------------------
// One layer: C[128, Nout] = A @ W, B streamed in 32-k chunks (double buffer).
// SKIP trailing ksteps whose B is entirely zero-padding.
// ---------------------------------------------------------------------------
#define BUFB 21760   // bytes per B staging buffer (max: 2*136*40*2)

template<int NPAD, int NT, int NCH, int SKIP, class GetA>
__device__ __forceinline__ void run_layer(const __nv_bfloat16* gB, float (&C)[17][4],
                                          char* sB, uint32_t sbB, int tid, int lane,
                                          GetA getA)
{
    constexpr int CHB = NPAD * 160;   // bytes per chunk (both splits)
    constexpr int CNT = NPAD * 10;    // 16B transfers per chunk
#pragma unroll
    for (int t = 0; t < NT; ++t) { C[t][0] = C[t][1] = C[t][2] = C[t][3] = 0.f; }

    __syncthreads();                  // prev layer done with sB
    {
        const char* src = (const char*)gB;
        for (int t = tid; t < CNT; t += THREADS) cp_async16(sB + t * 16, src + t * 16);
        cp_commit();
    }
#pragma unroll
    for (int c = 0; c < NCH; ++c) {
        cp_wait0();
        __syncthreads();
        if (c + 1 < NCH) {
            const char* src = (const char*)gB + (size_t)(c + 1) * CHB;
            char* dst = sB + ((c + 1) & 1) * BUFB;
            for (int t = tid; t < CNT; t += THREADS) cp_async16(dst + t * 16, src + t * 16);
            cp_commit();
        }
        const uint32_t bb = sbB + (uint32_t)((c & 1) * BUFB);
#pragma unroll
        for (int s2 = 0; s2 < 2; ++s2) {
            if (2 * c + s2 >= 2 * NCH - SKIP) continue;
            uint32_t fh[4], fl[4];
            getA(2 * c + s2, fh, fl);
            const uint32_t rowA = bb + (uint32_t)(lane & 7) * 80u
                                + ((lane & 8) ? 16u : 0u) + (uint32_t)(s2 * 32);
#pragma unroll
            for (int t = 0; t < NT; ++t) {
                uint32_t bh0, bh1, bl0, bl1;
                ldsm2(bh0, bh1, rowA + (uint32_t)(t * 640));
                ldsm2(bl0, bl1, rowA + (uint32_t)(t * 640 + NPAD * 80));
                mma_bf16(C[t], fh[0], fh[1], fh[2], fh[3], bh0, bh1);
                mma_bf16(C[t], fl[0], fl[1], fl[2], fl[3], bh0, bh1);
                mma_bf16(C[t], fh[0], fh[1], fh[2], fh[3], bl0, bl1);
            }
        }
    }
}

// ---------------------------------------------------------------------------
// smem: sB double buffer (2*21760) then enc_p packed hi/lo [128][41] u32 each
// ---------------------------------------------------------------------------
#define SMEM_ENC  (2 * BUFB)
#define SMEM_BYTES (2 * BUFB + 2 * 128 * 41 * 4)

__global__ void __launch_bounds__(THREADS)
FusedDynamicNeRF_hmma(const float* __restrict__ x, float* __restrict__ out, const int N)
{
    extern __shared__ __align__(16) char smem[];
    char* sB = smem;
    uint32_t* sEncH = (uint32_t*)(smem + SMEM_ENC);
    uint32_t* sEncL = sEncH + 128 * 41;
    const uint32_t sbB = (uint32_t)__cvta_generic_to_shared(smem);

    const int tid  = threadIdx.x;
    const int lane = tid & 31;
    const int q    = lane & 3;
    const int wrow = (tid >> 5) * 16;             // warp's m-base (0..112)
    const int base = blockIdx.x * MTILE;
    const float PI_F = 3.14159265358979f;

    // ---- enc_p -> smem packed bf16x2 hi/lo: [row][kpair 0..39] ----
    for (int idx = tid; idx < 128 * 40; idx += THREADS) {
        const int row = idx / 40;
        const int kp  = idx - row * 40;
        const int d   = kp / 10;
        const int cc0 = 2 * kp - 20 * d;          // 0..18 even
        const int i   = base + row;
        const float xv = (i < N) ? x[i * 7 + d] : 0.0f;
        float v[2];
#pragma unroll
        for (int u = 0; u < 2; ++u) {
            const int cc = cc0 + u;
            const int j  = (cc < 10) ? cc : cc - 10;
            const float freq = PI_F * __int_as_float((127 + j) << 23);
            float s, c;
            acc_sincos(xv * freq, &s, &c);
            v[u] = (cc < 10) ? s : c;
        }
        uint32_t h, l;
        split2(v[0], v[1], h, l);
        sEncH[row * 41 + kp] = h;
        sEncL[row * 41 + kp] = l;
    }

    float C[17][4];
    uint32_t AH[8][4], AL[8][4];

    auto encA = [&](int s, uint32_t* fh, uint32_t* fl) {
        const int rr  = wrow + (lane >> 2);
        const int kpi = 8 * s + q;
        fh[0] = sEncH[rr * 41 + kpi];        fh[1] = sEncH[(rr + 8) * 41 + kpi];
        fh[2] = sEncH[rr * 41 + kpi + 4];    fh[3] = sEncH[(rr + 8) * 41 + kpi + 4];
        fl[0] = sEncL[rr * 41 + kpi];        fl[1] = sEncL[(rr + 8) * 41 + kpi];
        fl[2] = sEncL[rr * 41 + kpi + 4];    fl[3] = sEncL[(rr + 8) * 41 + kpi + 4];
    };
    auto regA = [&](int s, uint32_t* fh, uint32_t* fl) {
#pragma unroll
        for (int j = 0; j < 4; ++j) { fh[j] = AH[s][j]; fl[j] = AL[s][j]; }
    };

    // L0: enc_p(80) -> 128, relu. chunks=3 (K pad 96), skip kstep5 (B zero).
    run_layer<128, 16, 3, 1>(g_wpk + 0, C, sB, sbB, tid, lane, encA);
    c_to_a<8, true, 0>(C, AH, AL);
    // L1
    run_layer<128, 16, 4, 0>(g_wpk + 30720, C, sB, sbB, tid, lane, regA);
    c_to_a<8, true, 0>(C, AH, AL);
    // L2 (part1, no relu)
    run_layer<128, 16, 4, 0>(g_wpk + 71680, C, sB, sbB, tid, lane, regA);
    c_to_a<8, false, 0>(C, AH, AL);
    // L3: concat(enc_p, part1) K=208 (pad 224, skip kstep13)
    run_layer<128, 16, 7, 1>(g_wpk + 112640, C, sB, sbB, tid, lane,
        [&](int s, uint32_t* fh, uint32_t* fl) {
            if (s < 5) encA(s, fh, fl);
            else {
#pragma unroll
                for (int j = 0; j < 4; ++j) { fh[j] = AH[s - 5][j]; fl[j] = AL[s - 5][j]; }
            }
        });
    c_to_a<8, true, 0>(C, AH, AL);
    // L4, L5
    run_layer<128, 16, 4, 0>(g_wpk + 184320, C, sB, sbB, tid, lane, regA);
    c_to_a<8, true, 0>(C, AH, AL);
    run_layer<128, 16, 4, 0>(g_wpk + 225280, C, sB, sbB, tid, lane, regA);
    c_to_a<8, true, 0>(C, AH, AL);
    // L6: dens_out, N=136 (17 tiles), no relu
    run_layer<136, 17, 4, 0>(g_wpk + 266240, C, sB, sbB, tid, lane, regA);

    // ---- L6 outputs: density(3), flow tanh(4..9), disocc sigmoid(10,11) ----
    {
        const int i0 = base + wrow + (lane >> 2);
        const int i1 = i0 + 8;
        if (q < 3) {
            if (i0 < N) {
                out[i0 * 12 + 4 + 2 * q] = acc_tanh(C[0][0]);
                out[i0 * 12 + 5 + 2 * q] = acc_tanh(C[0][1]);
            }
            if (i1 < N) {
                out[i1 * 12 + 4 + 2 * q] = acc_tanh(C[0][2]);
                out[i1 * 12 + 5 + 2 * q] = acc_tanh(C[0][3]);
            }
        } else {
            if (i0 < N) {
                out[i0 * 12 + 10] = acc_sigmoid(C[0][0]);
                out[i0 * 12 + 11] = acc_sigmoid(C[0][1]);
            }
            if (i1 < N) {
                out[i1 * 12 + 10] = acc_sigmoid(C[0][2]);
                out[i1 * 12 + 11] = acc_sigmoid(C[0][3]);
            }
        }
        if (q == 0) {
            if (i0 < N) out[i0 * 12 + 3] = C[1][0];
            if (i1 < N) out[i1 * 12 + 3] = C[1][2];
        }
    }

    // ---- build L7 A: enc_v (k0..23) + feature (k24..151) + pad zeros ----
    uint32_t E0h[4], E0l[4], E1h[4], E1l[4];
    {
        float vA[6], vB[6];
#pragma unroll
        for (int rh = 0; rh < 2; ++rh) {
            const int i = base + wrow + (lane >> 2) + 8 * rh;
            float xv[3];
#pragma unroll
            for (int d = 0; d < 3; ++d) xv[d] = (i < N) ? x[i * 7 + 4 + d] : 0.0f;
            float* v = rh ? vB : vA;
            const int cols[6] = {2 * q, 2 * q + 1, 2 * q + 8, 2 * q + 9, 16 + 2 * q, 17 + 2 * q};
#pragma unroll
            for (int u = 0; u < 6; ++u) {
                const int c  = cols[u];
                const int d  = c >> 3;
                const int jj = c & 7;
                const int j  = jj & 3;
                const float freq = PI_F * __int_as_float((127 + j) << 23);
                float s, cc;
                acc_sincos(xv[d] * freq, &s, &cc);
                v[u] = (jj < 4) ? s : cc;
            }
        }
        split2(vA[0], vA[1], E0h[0], E0l[0]);
        split2(vB[0], vB[1], E0h[1], E0l[1]);
        split2(vA[2], vA[3], E0h[2], E0l[2]);
        split2(vB[2], vB[3], E0h[3], E0l[3]);
        split2(vA[4], vA[5], E1h[0], E1l[0]);
        split2(vB[4], vB[5], E1h[1], E1l[1]);
        split2(C[1][0], C[1][1], E1h[2], E1l[2]);   // feature cols 0..7 (tile1)
        split2(C[1][2], C[1][3], E1h[3], E1l[3]);
    }
    c_to_a<7, false, 2>(C, AH, AL);                 // ksteps 2..8 <- tiles 2..15
    {   // kstep 9: tile16 + zero pad
        uint32_t h01, h23, l01, l23;
        split2(C[16][0], C[16][1], h01, l01);
        split2(C[16][2], C[16][3], h23, l23);
        AH[7][0] = h01; AH[7][1] = h23; AH[7][2] = 0; AH[7][3] = 0;
        AL[7][0] = l01; AL[7][1] = l23; AL[7][2] = 0; AL[7][3] = 0;
    }
    // L7: K=152 (pad 160), relu
    run_layer<128, 16, 5, 0>(g_wpk + 309760, C, sB, sbB, tid, lane,
        [&](int s, uint32_t* fh, uint32_t* fl) {
            if (s == 0) {
#pragma unroll
                for (int j = 0; j < 4; ++j) { fh[j] = E0h[j]; fl[j] = E0l[j]; }
            } else if (s == 1) {
#pragma unroll
                for (int j = 0; j < 4; ++j) { fh[j] = E1h[j]; fl[j] = E1l[j]; }
            } else {
#pragma unroll
                for (int j = 0; j < 4; ++j) { fh[j] = AH[s - 2][j]; fl[j] = AL[s - 2][j]; }
            }
        });
    c_to_a<8, true, 0>(C, AH, AL);
    // L8: N=3 (pad 8), 1 tile
    run_layer<8, 1, 4, 0>(g_wpk + 360960, C, sB, sbB, tid, lane, regA);

    // ---- rgb ----
    {
        const int i0 = base + wrow + (lane >> 2);
        const int i1 = i0 + 8;
        if (q == 0) {
            if (i0 < N) { out[i0 * 12 + 0] = C[0][0]; out[i0 * 12 + 1] = C[0][1]; }
            if (i1 < N) { out[i1 * 12 + 0] = C[0][2]; out[i1 * 12 + 1] = C[0][3]; }
        } else if (q == 1) {
            if (i0 < N) out[i0 * 12 + 2] = C[0][0];
            if (i1 < N) out[i1 * 12 + 2] = C[0][2];
        }
    }
}

extern "C" void kernel_launch(void* const* d_in, const int* in_sizes, int n_in,
                              void* d_out, int out_size)
{
    (void)n_in; (void)out_size;
    const float* x = (const float*)d_in[0];
    float* out = (float*)d_out;
    const int N = in_sizes[0] / 7;

    repack_kernel<<<dim3(64, 9), 256>>>(
        (const float*)d_in[1], (const float*)d_in[2], (const float*)d_in[3],
        (const float*)d_in[4], (const float*)d_in[5], (const float*)d_in[6],
        (const float*)d_in[7], (const float*)d_in[8], (const float*)d_in[9]);

    cudaFuncSetAttribute(FusedDynamicNeRF_hmma,
                         cudaFuncAttributeMaxDynamicSharedMemorySize, SMEM_BYTES);
    const int blocks = (N + MTILE - 1) / MTILE;
    FusedDynamicNeRF_hmma<<<blocks, THREADS, SMEM_BYTES>>>(x, out, N);
}

// round 16
// speedup vs baseline: 4.0825x; 1.3004x over previous
#include <cuda_runtime.h>
#include <cuda_bf16.h>
#include <math.h>
#include <stdint.h>

#define THREADS 128
#define MTILE   64

// ---------------------------------------------------------------------------
// Repacked B in global scratch: per layer, chunks of 32 k-columns.
// Chunk layout: [2 splits (hi,lo)][Npad rows(n)][40 bf16 (32 k + 8 pad)]
// so ldmatrix rows are 80B apart (bank-stagger -> conflict-free).
// ---------------------------------------------------------------------------
#define WPK_ELEMS 363520
__device__ __align__(16) __nv_bfloat16 g_wpk[WPK_ELEMS];

__global__ void repack_kernel(
    const float* w0, const float* w1, const float* w2, const float* w3,
    const float* w4, const float* w5, const float* w6, const float* w7,
    const float* w8)
{
    const int KR[9]  = {80,128,128,208,128,128,128,152,128};
    const int NR[9]  = {128,128,128,128,128,128,136,128,3};
    const int NP[9]  = {128,128,128,128,128,128,136,128,8};
    const int NC[9]  = {3,4,4,7,4,4,4,5,4};
    const int OFF[9] = {0,30720,71680,112640,184320,225280,266240,309760,360960};
    const float* ws[9] = {w0,w1,w2,w3,w4,w5,w6,w7,w8};

    const int l = blockIdx.y;
    const float* W = ws[l];
    const int np = NP[l], nr = NR[l], kr = KR[l];
    const int per_chunk = 2 * np * 40;
    const int total = NC[l] * per_chunk;
    for (int idx = blockIdx.x * blockDim.x + threadIdx.x; idx < total;
         idx += gridDim.x * blockDim.x) {
        const int c    = idx / per_chunk;
        int rem        = idx - c * per_chunk;
        const int sg   = rem / (np * 40);
        rem           -= sg * (np * 40);
        const int n    = rem / 40;
        const int kk   = rem - n * 40;
        const int k    = c * 32 + kk;
        float v = 0.0f;
        if (kk < 32 && k < kr && n < nr) v = W[k * nr + n];
        const __nv_bfloat16 h = __float2bfloat16_rn(v);
        if (sg == 0) g_wpk[OFF[l] + idx] = h;
        else {
            const float r = v - __bfloat162float(h);
            g_wpk[OFF[l] + idx] = __float2bfloat16_rn(r);
        }
    }
}

// ---------------------------------------------------------------------------
// Helpers
// ---------------------------------------------------------------------------
__device__ __forceinline__ void acc_sincos(float ang, float* s, float* c) {
    double dq = (double)ang * 0.3183098861837906715377675267450287;  // /pi
    double rq = fma(-2.0, rint(0.5 * dq), dq);                       // [-1,1]
    sincospif((float)rq, s, c);
}
__device__ __forceinline__ float acc_sigmoid(float v) { return 1.0f / (1.0f + expf(-v)); }
__device__ __forceinline__ float acc_tanh(float v) {
    float t = expf(-2.0f * fabsf(v));
    return copysignf((1.0f - t) / (1.0f + t), v);
}
__device__ __forceinline__ uint32_t packbf(float lo, float hi) {
    uint32_t r;
    asm("cvt.rn.bf16x2.f32 %0, %1, %2;" : "=r"(r) : "f"(hi), "f"(lo));
    return r;
}
__device__ __forceinline__ float bflo(uint32_t u) { return __uint_as_float(u << 16); }
__device__ __forceinline__ float bfhi(uint32_t u) { return __uint_as_float(u & 0xFFFF0000u); }
__device__ __forceinline__ void split2(float v0, float v1, uint32_t& h, uint32_t& l) {
    h = packbf(v0, v1);
    l = packbf(v0 - bflo(h), v1 - bfhi(h));
}
// volatile is load-bearing: non-volatile asm (no memory operand visible to the
// compiler) can be hoisted above cp.async.wait/__syncthreads or sunk past the
// buffer's overwrite. R14 (volatile) passed; R15 (non-volatile) corrupted.
__device__ __forceinline__ void ldsm2(uint32_t& r0, uint32_t& r1, uint32_t addr) {
    asm volatile("ldmatrix.sync.aligned.m8n8.x2.shared.b16 {%0,%1}, [%2];"
                 : "=r"(r0), "=r"(r1) : "r"(addr));
}
__device__ __forceinline__ void mma_bf16(float (&c)[4],
    uint32_t a0, uint32_t a1, uint32_t a2, uint32_t a3, uint32_t b0, uint32_t b1) {
    asm("mma.sync.aligned.m16n8k16.row.col.f32.bf16.bf16.f32 "
        "{%0,%1,%2,%3}, {%4,%5,%6,%7}, {%8,%9}, {%0,%1,%2,%3};"
        : "+f"(c[0]), "+f"(c[1]), "+f"(c[2]), "+f"(c[3])
        : "r"(a0), "r"(a1), "r"(a2), "r"(a3), "r"(b0), "r"(b1));
}
__device__ __forceinline__ void cp_async16(void* sdst, const void* gsrc) {
    unsigned s = (unsigned)__cvta_generic_to_shared(sdst);
    asm volatile("cp.async.ca.shared.global [%0], [%1], 16;" :: "r"(s), "l"(gsrc));
}
__device__ __forceinline__ void cp_commit() { asm volatile("cp.async.commit_group;"); }
__device__ __forceinline__ void cp_wait0()  {
    asm volatile("cp.async.wait_group 0;" ::: "memory");
}

// ---------------------------------------------------------------------------
// C-fragment -> next-layer A-fragments (registers, optional ReLU).
// ---------------------------------------------------------------------------
template<int NS, bool RELU, int T0>
__device__ __forceinline__ void c_to_a(const float (&C)[17][4],
                                       uint32_t (&AH)[8][4], uint32_t (&AL)[8][4]) {
#pragma unroll
    for (int s = 0; s < NS; ++s) {
#pragma unroll
        for (int half = 0; half < 2; ++half) {
            const int t = T0 + 2 * s + half;
            float c0 = C[t][0], c1 = C[t][1], c2 = C[t][2], c3 = C[t][3];
            if (RELU) {
                c0 = fmaxf(c0, 0.f); c1 = fmaxf(c1, 0.f);
                c2 = fmaxf(c2, 0.f); c3 = fmaxf(c3, 0.f);
            }
            uint32_t h01, h23, l01, l23;
            split2(c0, c1, h01, l01);
            split2(c2, c3, h23, l23);
            AH[s][2 * half]     = h01;  AH[s][2 * half + 1] = h23;
            AL[s][2 * half]     = l01;  AL[s][2 * half + 1] = l23;
        }
    }
}

// ---------------------------------------------------------------------------
// One layer, flat cross-layer pipeline: chunk c computed from buffer
// (bufp+c)&1 while chunk c+1 (or next layer's chunk 0) prefetches into the
// other buffer. Exactly one __syncthreads per chunk. The sync at chunk c
// guarantees all warps finished chunk c-1 (and, at c=0, the entire previous
// layer) before the prefetch that reuses that buffer is issued.
// ---------------------------------------------------------------------------
#define BUFB 21760   // bytes per B staging buffer (max chunk: 2*136*40*2)

template<int NPAD, int NT, int NCH, int SKIP, class GetA>
__device__ __forceinline__ void run_layer(
    const __nv_bfloat16* gB, const __nv_bfloat16* gBnext, int cntNext,
    int& bufp, float (&C)[17][4], char* sB, uint32_t sbB, int tid, int lane,
    GetA getA)
{
    constexpr int CHB = NPAD * 160;   // bytes per chunk (both splits)
    constexpr int CNT = NPAD * 10;    // 16B transfers per chunk
#pragma unroll
    for (int t = 0; t < NT; ++t) { C[t][0] = C[t][1] = C[t][2] = C[t][3] = 0.f; }

#pragma unroll
    for (int c = 0; c < NCH; ++c) {
        cp_wait0();            // chunk c resident
        __syncthreads();       // all warps past chunk c-1; buffer safe to reuse

        if (c + 1 < NCH) {
            const char* src = (const char*)gB + (size_t)(c + 1) * CHB;
            char* dst = sB + ((bufp + c + 1) & 1) * BUFB;
            for (int t = tid; t < CNT; t += THREADS) cp_async16(dst + t * 16, src + t * 16);
        } else if (gBnext) {   // prefetch next layer's chunk 0
            char* dst = sB + ((bufp + NCH) & 1) * BUFB;
            for (int t = tid; t < cntNext; t += THREADS)
                cp_async16(dst + t * 16, (const char*)gBnext + t * 16);
        }
        cp_commit();

        const uint32_t bb = sbB + (uint32_t)(((bufp + c) & 1) * BUFB);
#pragma unroll
        for (int s2 = 0; s2 < 2; ++s2) {
            if (2 * c + s2 >= 2 * NCH - SKIP) break;
            uint32_t fh[4], fl[4];
            getA(2 * c + s2, fh, fl);
            const uint32_t rowA = bb + (uint32_t)(lane & 7) * 80u
                                + ((lane & 8) ? 16u : 0u) + (uint32_t)(s2 * 32);
#pragma unroll
            for (int t = 0; t < NT; ++t) {
                uint32_t bh0, bh1, bl0, bl1;
                ldsm2(bh0, bh1, rowA + (uint32_t)(t * 640));
                ldsm2(bl0, bl1, rowA + (uint32_t)(t * 640 + NPAD * 80));
                mma_bf16(C[t], fh[0], fh[1], fh[2], fh[3], bh0, bh1);
                mma_bf16(C[t], fl[0], fl[1], fl[2], fl[3], bh0, bh1);
                mma_bf16(C[t], fh[0], fh[1], fh[2], fh[3], bl0, bl1);
            }
        }
    }
    bufp = (bufp + NCH) & 1;
}

// ---------------------------------------------------------------------------
// smem: sB double buffer (2*21760) + enc_p packed hi/lo [64][41] u32 each
// total 64512 B -> 2 CTAs/SM
// ---------------------------------------------------------------------------
#define SMEM_ENC  (2 * BUFB)
#define SMEM_BYTES (2 * BUFB + 2 * 64 * 41 * 4)

__global__ void __launch_bounds__(THREADS, 2)
FusedDynamicNeRF_hmma(const float* __restrict__ x, float* __restrict__ out, const int N)
{
    extern __shared__ __align__(16) char smem[];
    char* sB = smem;
    uint32_t* sEncH = (uint32_t*)(smem + SMEM_ENC);
    uint32_t* sEncL = sEncH + 64 * 41;
    const uint32_t sbB = (uint32_t)__cvta_generic_to_shared(smem);

    const int tid  = threadIdx.x;
    const int lane = tid & 31;
    const int q    = lane & 3;
    const int wrow = (tid >> 5) * 16;             // warp m-base (0..48)
    const int base = blockIdx.x * MTILE;
    const float PI_F = 3.14159265358979f;

    const __nv_bfloat16* P[9] = {
        g_wpk, g_wpk + 30720, g_wpk + 71680, g_wpk + 112640, g_wpk + 184320,
        g_wpk + 225280, g_wpk + 266240, g_wpk + 309760, g_wpk + 360960 };

    int bufp = 0;
    {   // prefetch L0 chunk 0 while computing enc_p
        for (int t = tid; t < 1280; t += THREADS)
            cp_async16(sB + t * 16, (const char*)P[0] + t * 16);
        cp_commit();
    }

    // ---- enc_p -> smem packed bf16x2 hi/lo: [row][kpair 0..39] ----
    for (int idx = tid; idx < MTILE * 40; idx += THREADS) {
        const int row = idx / 40;
        const int kp  = idx - row * 40;
        const int d   = kp / 10;
        const int cc0 = 2 * kp - 20 * d;
        const int i   = base + row;
        const float xv = (i < N) ? x[i * 7 + d] : 0.0f;
        float v[2];
#pragma unroll
        for (int u = 0; u < 2; ++u) {
            const int cc = cc0 + u;
            const int j  = (cc < 10) ? cc : cc - 10;
            const float freq = PI_F * __int_as_float((127 + j) << 23);
            float s, c;
            acc_sincos(xv * freq, &s, &c);
            v[u] = (cc < 10) ? s : c;
        }
        uint32_t h, l;
        split2(v[0], v[1], h, l);
        sEncH[row * 41 + kp] = h;
        sEncL[row * 41 + kp] = l;
    }

    float C[17][4];
    uint32_t AH[8][4], AL[8][4];

    auto encA = [&](int s, uint32_t* fh, uint32_t* fl) {
        const int rr  = wrow + (lane >> 2);
        const int kpi = 8 * s + q;
        fh[0] = sEncH[rr * 41 + kpi];        fh[1] = sEncH[(rr + 8) * 41 + kpi];
        fh[2] = sEncH[rr * 41 + kpi + 4];    fh[3] = sEncH[(rr + 8) * 41 + kpi + 4];
        fl[0] = sEncL[rr * 41 + kpi];        fl[1] = sEncL[(rr + 8) * 41 + kpi];
        fl[2] = sEncL[rr * 41 + kpi + 4];    fl[3] = sEncL[(rr + 8) * 41 + kpi + 4];
    };
    auto regA = [&](int s, uint32_t* fh, uint32_t* fl) {
#pragma unroll
        for (int j = 0; j < 4; ++j) { fh[j] = AH[s][j]; fl[j] = AL[s][j]; }
    };

    // L0: enc_p(80)->128, relu (skip zero kstep 5)
    run_layer<128, 16, 3, 1>(P[0], P[1], 1280, bufp, C, sB, sbB, tid, lane, encA);
    c_to_a<8, true, 0>(C, AH, AL);
    // L1
    run_layer<128, 16, 4, 0>(P[1], P[2], 1280, bufp, C, sB, sbB, tid, lane, regA);
    c_to_a<8, true, 0>(C, AH, AL);
    // L2 (part1, no relu)
    run_layer<128, 16, 4, 0>(P[2], P[3], 1280, bufp, C, sB, sbB, tid, lane, regA);
    c_to_a<8, false, 0>(C, AH, AL);
    // L3: concat(enc_p, part1) K=208 (skip zero kstep 13)
    run_layer<128, 16, 7, 1>(P[3], P[4], 1280, bufp, C, sB, sbB, tid, lane,
        [&](int s, uint32_t* fh, uint32_t* fl) {
            if (s < 5) encA(s, fh, fl);
            else {
#pragma unroll
                for (int j = 0; j < 4; ++j) { fh[j] = AH[s - 5][j]; fl[j] = AL[s - 5][j]; }
            }
        });
    c_to_a<8, true, 0>(C, AH, AL);
    // L4, L5
    run_layer<128, 16, 4, 0>(P[4], P[5], 1280, bufp, C, sB, sbB, tid, lane, regA);
    c_to_a<8, true, 0>(C, AH, AL);
    run_layer<128, 16, 4, 0>(P[5], P[6], 1360, bufp, C, sB, sbB, tid, lane, regA);
    c_to_a<8, true, 0>(C, AH, AL);
    // L6: dens_out, N=136 (17 tiles), no relu
    run_layer<136, 17, 4, 0>(P[6], P[7], 1280, bufp, C, sB, sbB, tid, lane, regA);

    // ---- L6 outputs: density(3), flow tanh(4..9), disocc sigmoid(10,11) ----
    {
        const int i0 = base + wrow + (lane >> 2);
        const int i1 = i0 + 8;
        if (q < 3) {
            if (i0 < N) {
                out[i0 * 12 + 4 + 2 * q] = acc_tanh(C[0][0]);
                out[i0 * 12 + 5 + 2 * q] = acc_tanh(C[0][1]);
            }
            if (i1 < N) {
                out[i1 * 12 + 4 + 2 * q] = acc_tanh(C[0][2]);
                out[i1 * 12 + 5 + 2 * q] = acc_tanh(C[0][3]);
            }
        } else {
            if (i0 < N) {
                out[i0 * 12 + 10] = acc_sigmoid(C[0][0]);
                out[i0 * 12 + 11] = acc_sigmoid(C[0][1]);
            }
            if (i1 < N) {
                out[i1 * 12 + 10] = acc_sigmoid(C[0][2]);
                out[i1 * 12 + 11] = acc_sigmoid(C[0][3]);
            }
        }
        if (q == 0) {
            if (i0 < N) out[i0 * 12 + 3] = C[1][0];
            if (i1 < N) out[i1 * 12 + 3] = C[1][2];
        }
    }

    // ---- build L7 A: enc_v (k0..23) + feature (k24..151) + pad zeros ----
    uint32_t E0h[4], E0l[4], E1h[4], E1l[4];
    {
        float vA[6], vB[6];
#pragma unroll
        for (int rh = 0; rh < 2; ++rh) {
            const int i = base + wrow + (lane >> 2) + 8 * rh;
            float xv[3];
#pragma unroll
            for (int d = 0; d < 3; ++d) xv[d] = (i < N) ? x[i * 7 + 4 + d] : 0.0f;
            float* v = rh ? vB : vA;
            const int cols[6] = {2 * q, 2 * q + 1, 2 * q + 8, 2 * q + 9, 16 + 2 * q, 17 + 2 * q};
#pragma unroll
            for (int u = 0; u < 6; ++u) {
                const int c  = cols[u];
                const int d  = c >> 3;
                const int jj = c & 7;
                const int j  = jj & 3;
                const float freq = PI_F * __int_as_float((127 + j) << 23);
                float s, cc;
                acc_sincos(xv[d] * freq, &s, &cc);
                v[u] = (jj < 4) ? s : cc;
            }
        }
        split2(vA[0], vA[1], E0h[0], E0l[0]);
        split2(vB[0], vB[1], E0h[1], E0l[1]);
        split2(vA[2], vA[3], E0h[2], E0l[2]);
        split2(vB[2], vB[3], E0h[3], E0l[3]);
        split2(vA[4], vA[5], E1h[0], E1l[0]);
        split2(vB[4], vB[5], E1h[1], E1l[1]);
        split2(C[1][0], C[1][1], E1h[2], E1l[2]);   // feature cols 0..7 (tile1)
        split2(C[1][2], C[1][3], E1h[3], E1l[3]);
    }
    c_to_a<7, false, 2>(C, AH, AL);                 // ksteps 2..8 <- tiles 2..15
    {   // kstep 9: tile16 + zero pad
        uint32_t h01, h23, l01, l23;
        split2(C[16][0], C[16][1], h01, l01);
        split2(C[16][2], C[16][3], h23, l23);
        AH[7][0] = h01; AH[7][1] = h23; AH[7][2] = 0; AH[7][3] = 0;
        AL[7][0] = l01; AL[7][1] = l23; AL[7][2] = 0; AL[7][3] = 0;
    }
    // L7: K=152 (pad 160), relu
    run_layer<128, 16, 5, 0>(P[7], P[8], 80, bufp, C, sB, sbB, tid, lane,
        [&](int s, uint32_t* fh, uint32_t* fl) {
            if (s == 0) {
#pragma unroll
                for (int j = 0; j < 4; ++j) { fh[j] = E0h[j]; fl[j] = E0l[j]; }
            } else if (s == 1) {
#pragma unroll
                for (int j = 0; j < 4; ++j) { fh[j] = E1h[j]; fl[j] = E1l[j]; }
            } else {
#pragma unroll
                for (int j = 0; j < 4; ++j) { fh[j] = AH[s - 2][j]; fl[j] = AL[s - 2][j]; }
            }
        });
    c_to_a<8, true, 0>(C, AH, AL);
    // L8: N=3 (pad 8), 1 tile
    run_layer<8, 1, 4, 0>(P[8], (const __nv_bfloat16*)nullptr, 0, bufp, C, sB, sbB,
                          tid, lane, regA);

    // ---- rgb ----
    {
        const int i0 = base + wrow + (lane >> 2);
        const int i1 = i0 + 8;
        if (q == 0) {
            if (i0 < N) { out[i0 * 12 + 0] = C[0][0]; out[i0 * 12 + 1] = C[0][1]; }
            if (i1 < N) { out[i1 * 12 + 0] = C[0][2]; out[i1 * 12 + 1] = C[0][3]; }
        } else if (q == 1) {
            if (i0 < N) out[i0 * 12 + 2] = C[0][0];
            if (i1 < N) out[i1 * 12 + 2] = C[0][2];
        }
    }
}

extern "C" void kernel_launch(void* const* d_in, const int* in_sizes, int n_in,
                              void* d_out, int out_size)
{
    (void)n_in; (void)out_size;
    const float* x = (const float*)d_in[0];
    float* out = (float*)d_out;
    const int N = in_sizes[0] / 7;

    repack_kernel<<<dim3(64, 9), 256>>>(
        (const float*)d_in[1], (const float*)d_in[2], (const float*)d_in[3],
        (const float*)d_in[4], (const float*)d_in[5], (const float*)d_in[6],
        (const float*)d_in[7], (const float*)d_in[8], (const float*)d_in[9]);

    cudaFuncSetAttribute(FusedDynamicNeRF_hmma,
                         cudaFuncAttributeMaxDynamicSharedMemorySize, SMEM_BYTES);
    const int blocks = (N + MTILE - 1) / MTILE;
    FusedDynamicNeRF_hmma<<<blocks, THREADS, SMEM_BYTES>>>(x, out, N);
}

// round 17
// speedup vs baseline: 4.3345x; 1.0617x over previous
#include <cuda_runtime.h>
#include <cuda_bf16.h>
#include <math.h>
#include <stdint.h>

#define THREADS 128
#define MTILE   64

// ---------------------------------------------------------------------------
// Repacked B in global scratch: per layer, chunks of 32 k-columns.
// Chunk layout: [2 splits (hi,lo)][Npad rows(n)][40 bf16 (32 k + 8 pad)]
// so ldmatrix rows are 80B apart (bank-stagger -> conflict-free).
// ---------------------------------------------------------------------------
#define WPK_ELEMS 363520
__device__ __align__(16) __nv_bfloat16 g_wpk[WPK_ELEMS];

__global__ void repack_kernel(
    const float* w0, const float* w1, const float* w2, const float* w3,
    const float* w4, const float* w5, const float* w6, const float* w7,
    const float* w8)
{
    const int KR[9]  = {80,128,128,208,128,128,128,152,128};
    const int NR[9]  = {128,128,128,128,128,128,136,128,3};
    const int NP[9]  = {128,128,128,128,128,128,136,128,8};
    const int NC[9]  = {3,4,4,7,4,4,4,5,4};
    const int OFF[9] = {0,30720,71680,112640,184320,225280,266240,309760,360960};
    const float* ws[9] = {w0,w1,w2,w3,w4,w5,w6,w7,w8};

    const int l = blockIdx.y;
    const float* W = ws[l];
    const int np = NP[l], nr = NR[l], kr = KR[l];
    const int per_chunk = 2 * np * 40;
    const int total = NC[l] * per_chunk;
    for (int idx = blockIdx.x * blockDim.x + threadIdx.x; idx < total;
         idx += gridDim.x * blockDim.x) {
        const int c    = idx / per_chunk;
        int rem        = idx - c * per_chunk;
        const int sg   = rem / (np * 40);
        rem           -= sg * (np * 40);
        const int n    = rem / 40;
        const int kk   = rem - n * 40;
        const int k    = c * 32 + kk;
        float v = 0.0f;
        if (kk < 32 && k < kr && n < nr) v = W[k * nr + n];
        const __nv_bfloat16 h = __float2bfloat16_rn(v);
        if (sg == 0) g_wpk[OFF[l] + idx] = h;
        else {
            const float r = v - __bfloat162float(h);
            g_wpk[OFF[l] + idx] = __float2bfloat16_rn(r);
        }
    }
}

// ---------------------------------------------------------------------------
// Helpers
// ---------------------------------------------------------------------------
__device__ __forceinline__ void acc_sincos(float ang, float* s, float* c) {
    double dq = (double)ang * 0.3183098861837906715377675267450287;  // /pi
    double rq = fma(-2.0, rint(0.5 * dq), dq);                       // [-1,1]
    sincospif((float)rq, s, c);
}
__device__ __forceinline__ float acc_sigmoid(float v) { return 1.0f / (1.0f + expf(-v)); }
__device__ __forceinline__ float acc_tanh(float v) {
    float t = expf(-2.0f * fabsf(v));
    return copysignf((1.0f - t) / (1.0f + t), v);
}
__device__ __forceinline__ uint32_t packbf(float lo, float hi) {
    uint32_t r;
    asm("cvt.rn.bf16x2.f32 %0, %1, %2;" : "=r"(r) : "f"(hi), "f"(lo));
    return r;
}
__device__ __forceinline__ float bflo(uint32_t u) { return __uint_as_float(u << 16); }
__device__ __forceinline__ float bfhi(uint32_t u) { return __uint_as_float(u & 0xFFFF0000u); }
__device__ __forceinline__ void split2(float v0, float v1, uint32_t& h, uint32_t& l) {
    h = packbf(v0, v1);
    l = packbf(v0 - bflo(h), v1 - bfhi(h));
}
// volatile is load-bearing on all ldmatrix: non-volatile asm can be hoisted
// above cp.async.wait/__syncthreads or sunk past the buffer's overwrite.
// R14 (volatile) passed; R15 (non-volatile) corrupted.
__device__ __forceinline__ void ldsm2(uint32_t& r0, uint32_t& r1, uint32_t addr) {
    asm volatile("ldmatrix.sync.aligned.m8n8.x2.shared.b16 {%0,%1}, [%2];"
                 : "=r"(r0), "=r"(r1) : "r"(addr));
}
__device__ __forceinline__ void ldsm4(uint32_t* r, uint32_t addr) {
    asm volatile("ldmatrix.sync.aligned.m8n8.x4.shared.b16 {%0,%1,%2,%3}, [%4];"
                 : "=r"(r[0]), "=r"(r[1]), "=r"(r[2]), "=r"(r[3]) : "r"(addr));
}
__device__ __forceinline__ void mma_bf16(float (&c)[4],
    uint32_t a0, uint32_t a1, uint32_t a2, uint32_t a3, uint32_t b0, uint32_t b1) {
    asm("mma.sync.aligned.m16n8k16.row.col.f32.bf16.bf16.f32 "
        "{%0,%1,%2,%3}, {%4,%5,%6,%7}, {%8,%9}, {%0,%1,%2,%3};"
        : "+f"(c[0]), "+f"(c[1]), "+f"(c[2]), "+f"(c[3])
        : "r"(a0), "r"(a1), "r"(a2), "r"(a3), "r"(b0), "r"(b1));
}
__device__ __forceinline__ void cp_async16(void* sdst, const void* gsrc) {
    unsigned s = (unsigned)__cvta_generic_to_shared(sdst);
    asm volatile("cp.async.ca.shared.global [%0], [%1], 16;" :: "r"(s), "l"(gsrc));
}
__device__ __forceinline__ void cp_commit() { asm volatile("cp.async.commit_group;"); }
__device__ __forceinline__ void cp_wait0()  {
    asm volatile("cp.async.wait_group 0;" ::: "memory");
}

// ---------------------------------------------------------------------------
// C-fragment -> next-layer A-fragments (registers, optional ReLU).
// ---------------------------------------------------------------------------
template<int NS, bool RELU, int T0>
__device__ __forceinline__ void c_to_a(const float (&C)[17][4],
                                       uint32_t (&AH)[8][4], uint32_t (&AL)[8][4]) {
#pragma unroll
    for (int s = 0; s < NS; ++s) {
#pragma unroll
        for (int half = 0; half < 2; ++half) {
            const int t = T0 + 2 * s + half;
            float c0 = C[t][0], c1 = C[t][1], c2 = C[t][2], c3 = C[t][3];
            if (RELU) {
                c0 = fmaxf(c0, 0.f); c1 = fmaxf(c1, 0.f);
                c2 = fmaxf(c2, 0.f); c3 = fmaxf(c3, 0.f);
            }
            uint32_t h01, h23, l01, l23;
            split2(c0, c1, h01, l01);
            split2(c2, c3, h23, l23);
            AH[s][2 * half]     = h01;  AH[s][2 * half + 1] = h23;
            AL[s][2 * half]     = l01;  AL[s][2 * half + 1] = l23;
        }
    }
}

// ---------------------------------------------------------------------------
// One layer, flat cross-layer pipeline: chunk c computed from buffer
// (bufp+c)&1 while chunk c+1 (or next layer's chunk 0) prefetches into the
// other buffer. One __syncthreads per chunk.
// Inner loop: ldsm4 loads TWO n-tiles' B fragments per instruction; the
// fragments for pair tp+1 are issued (volatile, in-order) BEFORE the 6 MMAs
// of pair tp, so ~48cyc of tensor work hides the ~33cyc LDSM latency.
// ---------------------------------------------------------------------------
#define BUFB 21760   // bytes per B staging buffer (max chunk: 2*136*40*2)

template<int NPAD, int NT, int NCH, int SKIP, class GetA>
__device__ __forceinline__ void run_layer(
    const __nv_bfloat16* gB, const __nv_bfloat16* gBnext, int cntNext,
    int& bufp, float (&C)[17][4], char* sB, uint32_t sbB, int tid, int lane,
    GetA getA)
{
    constexpr int CHB   = NPAD * 160;   // bytes per chunk (both splits)
    constexpr int CNT   = NPAD * 10;    // 16B transfers per chunk
    constexpr int NPAIR = NT / 2;       // ldsm4 tile-pairs
#pragma unroll
    for (int t = 0; t < NT; ++t) { C[t][0] = C[t][1] = C[t][2] = C[t][3] = 0.f; }

#pragma unroll
    for (int c = 0; c < NCH; ++c) {
        cp_wait0();            // chunk c resident
        __syncthreads();       // all warps past chunk c-1; buffer safe to reuse

        if (c + 1 < NCH) {
            const char* src = (const char*)gB + (size_t)(c + 1) * CHB;
            char* dst = sB + ((bufp + c + 1) & 1) * BUFB;
            for (int t = tid; t < CNT; t += THREADS) cp_async16(dst + t * 16, src + t * 16);
        } else if (gBnext) {   // prefetch next layer's chunk 0
            char* dst = sB + ((bufp + NCH) & 1) * BUFB;
            for (int t = tid; t < cntNext; t += THREADS)
                cp_async16(dst + t * 16, (const char*)gBnext + t * 16);
        }
        cp_commit();

        const uint32_t bb = sbB + (uint32_t)(((bufp + c) & 1) * BUFB);
#pragma unroll
        for (int s2 = 0; s2 < 2; ++s2) {
            if (2 * c + s2 >= 2 * NCH - SKIP) break;
            uint32_t fh[4], fl[4];
            getA(2 * c + s2, fh, fl);
            const uint32_t r4 = bb + (uint32_t)(lane & 7) * 80u
                              + ((lane & 8) ? 16u : 0u) + ((lane & 16) ? 640u : 0u)
                              + (uint32_t)(s2 * 32);
            const uint32_t r2 = bb + (uint32_t)(lane & 7) * 80u
                              + ((lane & 8) ? 16u : 0u) + (uint32_t)(s2 * 32);

            uint32_t bh[2][4], bl[2][4];
            if (NPAIR > 0) {                     // prologue: pair 0
                ldsm4(bh[0], r4);
                ldsm4(bl[0], r4 + (uint32_t)(NPAD * 80));
            }
#pragma unroll
            for (int tp = 0; tp < NPAIR; ++tp) {
                const int cur = tp & 1;
                if (tp + 1 < NPAIR) {            // prefetch pair tp+1 fragments
                    ldsm4(bh[cur ^ 1], r4 + (uint32_t)((tp + 1) * 1280));
                    ldsm4(bl[cur ^ 1], r4 + (uint32_t)((tp + 1) * 1280 + NPAD * 80));
                }
                const int t0 = 2 * tp, t1 = 2 * tp + 1;
                mma_bf16(C[t0], fh[0], fh[1], fh[2], fh[3], bh[cur][0], bh[cur][1]);
                mma_bf16(C[t1], fh[0], fh[1], fh[2], fh[3], bh[cur][2], bh[cur][3]);
                mma_bf16(C[t0], fl[0], fl[1], fl[2], fl[3], bh[cur][0], bh[cur][1]);
                mma_bf16(C[t1], fl[0], fl[1], fl[2], fl[3], bh[cur][2], bh[cur][3]);
                mma_bf16(C[t0], fh[0], fh[1], fh[2], fh[3], bl[cur][0], bl[cur][1]);
                mma_bf16(C[t1], fh[0], fh[1], fh[2], fh[3], bl[cur][2], bl[cur][3]);
            }
            if (NT & 1) {                        // odd tail tile
                const int t = NT - 1;
                uint32_t h0, h1, l0, l1;
                ldsm2(h0, h1, r2 + (uint32_t)(t * 640));
                ldsm2(l0, l1, r2 + (uint32_t)(t * 640 + NPAD * 80));
                mma_bf16(C[t], fh[0], fh[1], fh[2], fh[3], h0, h1);
                mma_bf16(C[t], fl[0], fl[1], fl[2], fl[3], h0, h1);
                mma_bf16(C[t], fh[0], fh[1], fh[2], fh[3], l0, l1);
            }
        }
    }
    bufp = (bufp + NCH) & 1;
}

// ---------------------------------------------------------------------------
// smem: sB double buffer (2*21760) + enc_p packed hi/lo [64][41] u32 each
// total 64512 B -> 2 CTAs/SM
// ---------------------------------------------------------------------------
#define SMEM_ENC  (2 * BUFB)
#define SMEM_BYTES (2 * BUFB + 2 * 64 * 41 * 4)

__global__ void __launch_bounds__(THREADS, 2)
FusedDynamicNeRF_hmma(const float* __restrict__ x, float* __restrict__ out, const int N)
{
    extern __shared__ __align__(16) char smem[];
    char* sB = smem;
    uint32_t* sEncH = (uint32_t*)(smem + SMEM_ENC);
    uint32_t* sEncL = sEncH + 64 * 41;
    const uint32_t sbB = (uint32_t)__cvta_generic_to_shared(smem);

    const int tid  = threadIdx.x;
    const int lane = tid & 31;
    const int q    = lane & 3;
    const int wrow = (tid >> 5) * 16;             // warp m-base (0..48)
    const int base = blockIdx.x * MTILE;
    const float PI_F = 3.14159265358979f;

    const __nv_bfloat16* P[9] = {
        g_wpk, g_wpk + 30720, g_wpk + 71680, g_wpk + 112640, g_wpk + 184320,
        g_wpk + 225280, g_wpk + 266240, g_wpk + 309760, g_wpk + 360960 };

    int bufp = 0;
    {   // prefetch L0 chunk 0 while computing enc_p
        for (int t = tid; t < 1280; t += THREADS)
            cp_async16(sB + t * 16, (const char*)P[0] + t * 16);
        cp_commit();
    }

    // ---- enc_p -> smem packed bf16x2 hi/lo: [row][kpair 0..39] ----
    for (int idx = tid; idx < MTILE * 40; idx += THREADS) {
        const int row = idx / 40;
        const int kp  = idx - row * 40;
        const int d   = kp / 10;
        const int cc0 = 2 * kp - 20 * d;
        const int i   = base + row;
        const float xv = (i < N) ? x[i * 7 + d] : 0.0f;
        float v[2];
#pragma unroll
        for (int u = 0; u < 2; ++u) {
            const int cc = cc0 + u;
            const int j  = (cc < 10) ? cc : cc - 10;
            const float freq = PI_F * __int_as_float((127 + j) << 23);
            float s, c;
            acc_sincos(xv * freq, &s, &c);
            v[u] = (cc < 10) ? s : c;
        }
        uint32_t h, l;
        split2(v[0], v[1], h, l);
        sEncH[row * 41 + kp] = h;
        sEncL[row * 41 + kp] = l;
    }

    float C[17][4];
    uint32_t AH[8][4], AL[8][4];

    auto encA = [&](int s, uint32_t* fh, uint32_t* fl) {
        const int rr  = wrow + (lane >> 2);
        const int kpi = 8 * s + q;
        fh[0] = sEncH[rr * 41 + kpi];        fh[1] = sEncH[(rr + 8) * 41 + kpi];
        fh[2] = sEncH[rr * 41 + kpi + 4];    fh[3] = sEncH[(rr + 8) * 41 + kpi + 4];
        fl[0] = sEncL[rr * 41 + kpi];        fl[1] = sEncL[(rr + 8) * 41 + kpi];
        fl[2] = sEncL[rr * 41 + kpi + 4];    fl[3] = sEncL[(rr + 8) * 41 + kpi + 4];
    };
    auto regA = [&](int s, uint32_t* fh, uint32_t* fl) {
#pragma unroll
        for (int j = 0; j < 4; ++j) { fh[j] = AH[s][j]; fl[j] = AL[s][j]; }
    };

    // L0: enc_p(80)->128, relu (skip zero kstep 5)
    run_layer<128, 16, 3, 1>(P[0], P[1], 1280, bufp, C, sB, sbB, tid, lane, encA);
    c_to_a<8, true, 0>(C, AH, AL);
    // L1
    run_layer<128, 16, 4, 0>(P[1], P[2], 1280, bufp, C, sB, sbB, tid, lane, regA);
    c_to_a<8, true, 0>(C, AH, AL);
    // L2 (part1, no relu)
    run_layer<128, 16, 4, 0>(P[2], P[3], 1280, bufp, C, sB, sbB, tid, lane, regA);
    c_to_a<8, false, 0>(C, AH, AL);
    // L3: concat(enc_p, part1) K=208 (skip zero kstep 13)
    run_layer<128, 16, 7, 1>(P[3], P[4], 1280, bufp, C, sB, sbB, tid, lane,
        [&](int s, uint32_t* fh, uint32_t* fl) {
            if (s < 5) encA(s, fh, fl);
            else {
#pragma unroll
                for (int j = 0; j < 4; ++j) { fh[j] = AH[s - 5][j]; fl[j] = AL[s - 5][j]; }
            }
        });
    c_to_a<8, true, 0>(C, AH, AL);
    // L4, L5
    run_layer<128, 16, 4, 0>(P[4], P[5], 1280, bufp, C, sB, sbB, tid, lane, regA);
    c_to_a<8, true, 0>(C, AH, AL);
    run_layer<128, 16, 4, 0>(P[5], P[6], 1360, bufp, C, sB, sbB, tid, lane, regA);
    c_to_a<8, true, 0>(C, AH, AL);
    // L6: dens_out, N=136 (17 tiles), no relu
    run_layer<136, 17, 4, 0>(P[6], P[7], 1280, bufp, C, sB, sbB, tid, lane, regA);

    // ---- L6 outputs: density(3), flow tanh(4..9), disocc sigmoid(10,11) ----
    {
        const int i0 = base + wrow + (lane >> 2);
        const int i1 = i0 + 8;
        if (q < 3) {
            if (i0 < N) {
                out[i0 * 12 + 4 + 2 * q] = acc_tanh(C[0][0]);
                out[i0 * 12 + 5 + 2 * q] = acc_tanh(C[0][1]);
            }
            if (i1 < N) {
                out[i1 * 12 + 4 + 2 * q] = acc_tanh(C[0][2]);
                out[i1 * 12 + 5 + 2 * q] = acc_tanh(C[0][3]);
            }
        } else {
            if (i0 < N) {
                out[i0 * 12 + 10] = acc_sigmoid(C[0][0]);
                out[i0 * 12 + 11] = acc_sigmoid(C[0][1]);
            }
            if (i1 < N) {
                out[i1 * 12 + 10] = acc_sigmoid(C[0][2]);
                out[i1 * 12 + 11] = acc_sigmoid(C[0][3]);
            }
        }
        if (q == 0) {
            if (i0 < N) out[i0 * 12 + 3] = C[1][0];
            if (i1 < N) out[i1 * 12 + 3] = C[1][2];
        }
    }

    // ---- build L7 A: enc_v (k0..23) + feature (k24..151) + pad zeros ----
    uint32_t E0h[4], E0l[4], E1h[4], E1l[4];
    {
        float vA[6], vB[6];
#pragma unroll
        for (int rh = 0; rh < 2; ++rh) {
            const int i = base + wrow + (lane >> 2) + 8 * rh;
            float xv[3];
#pragma unroll
            for (int d = 0; d < 3; ++d) xv[d] = (i < N) ? x[i * 7 + 4 + d] : 0.0f;
            float* v = rh ? vB : vA;
            const int cols[6] = {2 * q, 2 * q + 1, 2 * q + 8, 2 * q + 9, 16 + 2 * q, 17 + 2 * q};
#pragma unroll
            for (int u = 0; u < 6; ++u) {
                const int c  = cols[u];
                const int d  = c >> 3;
                const int jj = c & 7;
                const int j  = jj & 3;
                const float freq = PI_F * __int_as_float((127 + j) << 23);
                float s, cc;
                acc_sincos(xv[d] * freq, &s, &cc);
                v[u] = (jj < 4) ? s : cc;
            }
        }
        split2(vA[0], vA[1], E0h[0], E0l[0]);
        split2(vB[0], vB[1], E0h[1], E0l[1]);
        split2(vA[2], vA[3], E0h[2], E0l[2]);
        split2(vB[2], vB[3], E0h[3], E0l[3]);
        split2(vA[4], vA[5], E1h[0], E1l[0]);
        split2(vB[4], vB[5], E1h[1], E1l[1]);
        split2(C[1][0], C[1][1], E1h[2], E1l[2]);   // feature cols 0..7 (tile1)
        split2(C[1][2], C[1][3], E1h[3], E1l[3]);
    }
    c_to_a<7, false, 2>(C, AH, AL);                 // ksteps 2..8 <- tiles 2..15
    {   // kstep 9: tile16 + zero pad
        uint32_t h01, h23, l01, l23;
        split2(C[16][0], C[16][1], h01, l01);
        split2(C[16][2], C[16][3], h23, l23);
        AH[7][0] = h01; AH[7][1] = h23; AH[7][2] = 0; AH[7][3] = 0;
        AL[7][0] = l01; AL[7][1] = l23; AL[7][2] = 0; AL[7][3] = 0;
    }
    // L7: K=152 (pad 160), relu
    run_layer<128, 16, 5, 0>(P[7], P[8], 80, bufp, C, sB, sbB, tid, lane,
        [&](int s, uint32_t* fh, uint32_t* fl) {
            if (s == 0) {
#pragma unroll
                for (int j = 0; j < 4; ++j) { fh[j] = E0h[j]; fl[j] = E0l[j]; }
            } else if (s == 1) {
#pragma unroll
                for (int j = 0; j < 4; ++j) { fh[j] = E1h[j]; fl[j] = E1l[j]; }
            } else {
#pragma unroll
                for (int j = 0; j < 4; ++j) { fh[j] = AH[s - 2][j]; fl[j] = AL[s - 2][j]; }
            }
        });
    c_to_a<8, true, 0>(C, AH, AL);
    // L8: N=3 (pad 8), 1 tile
    run_layer<8, 1, 4, 0>(P[8], (const __nv_bfloat16*)nullptr, 0, bufp, C, sB, sbB,
                          tid, lane, regA);

    // ---- rgb ----
    {
        const int i0 = base + wrow + (lane >> 2);
        const int i1 = i0 + 8;
        if (q == 0) {
            if (i0 < N) { out[i0 * 12 + 0] = C[0][0]; out[i0 * 12 + 1] = C[0][1]; }
            if (i1 < N) { out[i1 * 12 + 0] = C[0][2]; out[i1 * 12 + 1] = C[0][3]; }
        } else if (q == 1) {
            if (i0 < N) out[i0 * 12 + 2] = C[0][0];
            if (i1 < N) out[i1 * 12 + 2] = C[0][2];
        }
    }
}

extern "C" void kernel_launch(void* const* d_in, const int* in_sizes, int n_in,
                              void* d_out, int out_size)
{
    (void)n_in; (void)out_size;
    const float* x = (const float*)d_in[0];
    float* out = (float*)d_out;
    const int N = in_sizes[0] / 7;

    repack_kernel<<<dim3(64, 9), 256>>>(
        (const float*)d_in[1], (const float*)d_in[2], (const float*)d_in[3],
        (const float*)d_in[4], (const float*)d_in[5], (const float*)d_in[6],
        (const float*)d_in[7], (const float*)d_in[8], (const float*)d_in[9]);

    cudaFuncSetAttribute(FusedDynamicNeRF_hmma,
                         cudaFuncAttributeMaxDynamicSharedMemorySize, SMEM_BYTES);
    const int blocks = (N + MTILE - 1) / MTILE;
    FusedDynamicNeRF_hmma<<<blocks, THREADS, SMEM_BYTES>>>(x, out, N);
}